// round 8
// baseline (speedup 1.0000x reference)
#include <cuda_runtime.h>
#include <cstdint>

#define HID 128
#define NGRAPHS 1024
#define ZD 56

// ---- graph-encoder scratch ----
__device__ float g_A   [100000 * 128];
__device__ float g_B   [100000 * 128];
__device__ float g_aggr[100000 * 128];
__device__ float g_sums[NGRAPHS * 128];
__device__ float g_cnt [NGRAPHS];
__device__ int   g_rowptr[100001];
__device__ int   g_cursor[100001];
__device__ int   g_csrsrc[400000];
__device__ int   g_bsums[128];
__device__ float g_wt  [161000];
// ---- tree-encoder scratch ----
__device__ float t_A   [20000 * 128];
__device__ float t_B   [20000 * 128];
__device__ float t_aggr[20000 * 128];
__device__ float t_sums[NGRAPHS * 128];
__device__ float t_cnt [NGRAPHS];
__device__ int   t_rowptr[20001];
__device__ int   t_cursor[20001];
__device__ int   t_csrsrc[40000];
__device__ int   t_bsums[128];
__device__ float t_wt  [161000];

// sH row stride (words): 136 ≡ 8 (mod 32) -> conflict-free LDS.64 a-frags
#define SH_STR 136
// sW chunk: 16 rows x 264 words; 264 ≡ 8 (mod 32) -> conflict-free LDS.64 b-frags
#define SWROW 264
#define WCHUNK (16 * SWROW)          // 4224 words per 32-k chunk
#define WMAT   (4 * WCHUNK)          // 16896 words per 128x128 matrix

// k-permutation within a row: fragment pairs (k, k+4) become adjacent words
__device__ __forceinline__ int kperm(int k) {
    return (k >> 5) * 32 + ((k >> 3) & 3) * 8 + (k & 3) * 2 + ((k >> 2) & 1);
}

__device__ __forceinline__ uint32_t f2tf32(float v) {
    uint32_t t;
    asm("cvt.rna.tf32.f32 %0, %1;" : "=r"(t) : "f"(v));
    return t;
}

__device__ __forceinline__ uint32_t smem_u32(const void* p) {
    return (uint32_t)__cvta_generic_to_shared(p);
}
__device__ __forceinline__ void cp16(uint32_t dst, const void* src) {
    asm volatile("cp.async.cg.shared.global [%0], [%1], 16;" :: "r"(dst), "l"(src));
}
__device__ __forceinline__ void cp16z(uint32_t dst, const void* src, int srcsz) {
    asm volatile("cp.async.cg.shared.global [%0], [%1], 16, %2;"
                 :: "r"(dst), "l"(src), "r"(srcsz));
}
#define CP_COMMIT() asm volatile("cp.async.commit_group;")
template<int N> __device__ __forceinline__ void cp_wait() {
    asm volatile("cp.async.wait_group %0;" :: "n"(N));
}

// One 32-k chunk of MMAs. sH rows stride hstr (permuted k at base hk0);
// sW is one permuted 16x264 chunk. All fragment loads are LDS.64.
__device__ __forceinline__ void mma_chunk(float c[2][8][4],
                                          const uint32_t* __restrict__ sH, int hk0, int hstr,
                                          const uint32_t* __restrict__ sW,
                                          int wm, int wn, int g, int tg)
{
#pragma unroll
    for (int kk4 = 0; kk4 < 4; kk4++) {
        uint32_t a[2][4], b[8][2];
#pragma unroll
        for (int mi = 0; mi < 2; mi++) {
            int r = wm + mi * 16 + g;
            uint2 p0 = *(const uint2*)&sH[r * hstr + hk0 + kk4 * 8 + tg * 2];
            uint2 p1 = *(const uint2*)&sH[(r + 8) * hstr + hk0 + kk4 * 8 + tg * 2];
            a[mi][0] = p0.x; a[mi][2] = p0.y;
            a[mi][1] = p1.x; a[mi][3] = p1.y;
        }
#pragma unroll
        for (int ni = 0; ni < 8; ni++) {
            int n = wn + ni * 8 + g;
            uint2 q = *(const uint2*)&sW[(kk4 * 4 + tg) * SWROW + n * 2];
            b[ni][0] = q.x; b[ni][1] = q.y;
        }
#pragma unroll
        for (int mi = 0; mi < 2; mi++)
#pragma unroll
            for (int ni = 0; ni < 8; ni++) {
                asm volatile(
                    "mma.sync.aligned.m16n8k8.row.col.f32.tf32.tf32.f32 "
                    "{%0,%1,%2,%3},{%4,%5,%6,%7},{%8,%9},{%0,%1,%2,%3};"
                    : "+f"(c[mi][ni][0]), "+f"(c[mi][ni][1]),
                      "+f"(c[mi][ni][2]), "+f"(c[mi][ni][3])
                    : "r"(a[mi][0]), "r"(a[mi][1]), "r"(a[mi][2]), "r"(a[mi][3]),
                      "r"(b[ni][0]), "r"(b[ni][1]));
            }
    }
}

// ---------------------------------------------------------------------------
// Fused node update. Weights pre-permuted+padded tf32 chunks (WCHUNK words).
// X raw (xcvt=1, layer 0) or permuted-tf32 aggr rows (xcvt=0).
// ---------------------------------------------------------------------------
__global__ __launch_bounds__(256, 2)
void fused_layer(const float* __restrict__ X, int K, int M, int xcvt,
                 const float* __restrict__ Wmain, const float* __restrict__ bmain,
                 const float* __restrict__ Wtop,  const float* __restrict__ btop,
                 const float* __restrict__ Wbot,
                 float* __restrict__ Aout, float* __restrict__ Bout)
{
    __shared__ uint32_t sH[128 * SH_STR];
    __shared__ uint32_t sW[2][WCHUNK];
    const int tid  = threadIdx.x;
    const int warp = tid >> 5, lane = tid & 31;
    const int g  = lane >> 2;
    const int tg = lane & 3;
    const int wm = (warp >> 1) * 32;
    const int wn = (warp & 1) * 64;
    const int row0 = blockIdx.x * 128;

    const int n1 = K >> 5;
    const int total = n1 + 8;

    auto wsrc = [&](int i) -> const float* {
        if (i < n1) return Wmain + (size_t)i * WCHUNK;
        int j = i - n1;
        return (j < 4) ? (Wtop + (size_t)j * WCHUNK) : (Wbot + (size_t)(j - 4) * WCHUNK);
    };
    auto issue_w = [&](int i, int buf) {
        const float* src = wsrc(i);
        uint32_t base = smem_u32(&sW[buf][0]);
        for (int s = tid; s < WCHUNK / 4; s += 256)
            cp16(base + (uint32_t)s * 16, src + s * 4);
    };

    if (!xcvt) {   // aggr rows already permuted tf32: raw async copy
        uint32_t base = smem_u32(sH);
        for (int s = tid; s < 128 * 32; s += 256) {
            int row = s >> 5, c4 = s & 31;
            const float* src = X + (size_t)(row0 + row) * 128 + c4 * 4;
            cp16z(base + (uint32_t)(row * SH_STR + c4 * 4) * 4, src,
                  (row0 + row < M) ? 16 : 0);
        }
    }
    issue_w(0, 0); CP_COMMIT();
    issue_w(1, 1); CP_COMMIT();
    if (xcvt) {    // layer 0: convert + permute raw input (K = 32 or 64)
        int ksh = (K == 32) ? 5 : 6;
        for (int i = tid; i < 128 * K; i += 256) {
            int r = i >> ksh, k = i & (K - 1);
            int row = row0 + r;
            float v = (row < M) ? X[(size_t)row * K + k] : 0.0f;
            sH[r * SH_STR + kperm(k)] = f2tf32(v);
        }
    }

    float c[2][8][4];
#pragma unroll
    for (int mi = 0; mi < 2; mi++)
#pragma unroll
        for (int ni = 0; ni < 8; ni++)
#pragma unroll
            for (int q = 0; q < 4; q++) c[mi][ni][q] = 0.0f;

    for (int i = 0; i < total; i++) {
        if (i + 2 < total) cp_wait<1>(); else cp_wait<0>();
        __syncthreads();
        int hk0 = ((i < n1) ? i : ((i - n1) & 3)) * 32;
        mma_chunk(c, sH, hk0, SH_STR, &sW[i & 1][0], wm, wn, g, tg);
        __syncthreads();
        if (i + 2 < total) { issue_w(i + 2, i & 1); CP_COMMIT(); }

        if (i == n1 - 1) {
            // h = relu(c + bmain) -> sH, permuted tf32; reset c
#pragma unroll
            for (int mi = 0; mi < 2; mi++)
#pragma unroll
                for (int half = 0; half < 2; half++) {
                    int r = wm + mi * 16 + g + half * 8;
#pragma unroll
                    for (int ni = 0; ni < 8; ni++) {
                        int col = wn + ni * 8 + tg * 2;
                        float vx = fmaxf(c[mi][ni][half * 2 + 0] + bmain[col],     0.f);
                        float vy = fmaxf(c[mi][ni][half * 2 + 1] + bmain[col + 1], 0.f);
                        sH[r * SH_STR + kperm(col)]     = f2tf32(vx);
                        sH[r * SH_STR + kperm(col + 1)] = f2tf32(vy);
                    }
                }
#pragma unroll
            for (int mi = 0; mi < 2; mi++)
#pragma unroll
                for (int ni = 0; ni < 8; ni++)
#pragma unroll
                    for (int q = 0; q < 4; q++) c[mi][ni][q] = 0.0f;
        } else if (i == n1 + 3) {
#pragma unroll
            for (int mi = 0; mi < 2; mi++)
#pragma unroll
                for (int half = 0; half < 2; half++) {
                    int row = row0 + wm + mi * 16 + g + half * 8;
                    if (row < M) {
#pragma unroll
                        for (int ni = 0; ni < 8; ni++) {
                            int col = wn + ni * 8 + tg * 2;
                            float2 o;
                            o.x = c[mi][ni][half * 2 + 0] + btop[col];
                            o.y = c[mi][ni][half * 2 + 1] + btop[col + 1];
                            *(float2*)(Aout + (size_t)row * 128 + col) = o;
                        }
                    }
                }
#pragma unroll
            for (int mi = 0; mi < 2; mi++)
#pragma unroll
                for (int ni = 0; ni < 8; ni++)
#pragma unroll
                    for (int q = 0; q < 4; q++) c[mi][ni][q] = 0.0f;
        } else if (i == total - 1) {
#pragma unroll
            for (int mi = 0; mi < 2; mi++)
#pragma unroll
                for (int half = 0; half < 2; half++) {
                    int row = row0 + wm + mi * 16 + g + half * 8;
                    if (row < M) {
#pragma unroll
                        for (int ni = 0; ni < 8; ni++) {
                            int col = wn + ni * 8 + tg * 2;
                            float2 o;
                            o.x = c[mi][ni][half * 2 + 0];
                            o.y = c[mi][ni][half * 2 + 1];
                            *(float2*)(Bout + (size_t)row * 128 + col) = o;
                        }
                    }
                }
        }
    }
}

// ---------------------------------------------------------------------------
// Final-layer GEMM + mean-pool epilogue (X = permuted aggr, W permuted).
// ---------------------------------------------------------------------------
#define SX_STR 40   // 40 ≡ 8 (mod 32)
__global__ __launch_bounds__(256, 2)
void gemm_pool(const float* __restrict__ X, const float* __restrict__ W,
               const float* __restrict__ bias, int M,
               const int* __restrict__ batch, float* __restrict__ sums)
{
    __shared__ uint32_t sX[2][128 * SX_STR];
    __shared__ uint32_t sW[2][WCHUNK];
    const int tid  = threadIdx.x;
    const int warp = tid >> 5, lane = tid & 31;
    const int g  = lane >> 2;
    const int tg = lane & 3;
    const int wm = (warp >> 1) * 32;
    const int wn = (warp & 1) * 64;
    const int row0 = blockIdx.x * 128;

    auto issue = [&](int i, int buf) {
        uint32_t xb = smem_u32(&sX[buf][0]);
        uint32_t wb = smem_u32(&sW[buf][0]);
        const float* xs = X + (size_t)row0 * 128 + i * 32;
        const float* ws = W + (size_t)i * WCHUNK;
#pragma unroll
        for (int s = tid; s < 1024; s += 256) {
            int row = s >> 3, c4 = s & 7;
            cp16z(xb + (uint32_t)(row * SX_STR + c4 * 4) * 4,
                  xs + (size_t)row * 128 + c4 * 4,
                  (row0 + row < M) ? 16 : 0);
        }
        for (int s = tid; s < WCHUNK / 4; s += 256)
            cp16(wb + (uint32_t)s * 16, ws + s * 4);
    };

    issue(0, 0); CP_COMMIT();
    issue(1, 1); CP_COMMIT();

    float c[2][8][4];
#pragma unroll
    for (int mi = 0; mi < 2; mi++)
#pragma unroll
        for (int ni = 0; ni < 8; ni++)
#pragma unroll
            for (int q = 0; q < 4; q++) c[mi][ni][q] = 0.0f;

    for (int i = 0; i < 4; i++) {
        if (i + 2 < 4) cp_wait<1>(); else cp_wait<0>();
        __syncthreads();
        mma_chunk(c, &sX[i & 1][0], 0, SX_STR, &sW[i & 1][0], wm, wn, g, tg);
        __syncthreads();
        if (i + 2 < 4) { issue(i + 2, i & 1); CP_COMMIT(); }
    }

#pragma unroll
    for (int mi = 0; mi < 2; mi++)
#pragma unroll
        for (int half = 0; half < 2; half++) {
            int row = row0 + wm + mi * 16 + g + half * 8;
            if (row < M) {
                int gsel = __ldg(batch + row);
#pragma unroll
                for (int ni = 0; ni < 8; ni++) {
                    int col = wn + ni * 8 + tg * 2;
                    float ox = fmaxf(c[mi][ni][half * 2 + 0] + bias[col],     0.f);
                    float oy = fmaxf(c[mi][ni][half * 2 + 1] + bias[col + 1], 0.f);
                    float* p = sums + (size_t)gsel * 128 + col;
                    asm volatile("red.global.add.v2.f32 [%0], {%1,%2};"
                                 :: "l"(p), "f"(ox), "f"(oy) : "memory");
                }
            }
        }
}

// ---------------------------------------------------------------------------
// Weight conversion: nmat 128x128 matrices -> permuted padded tf32 chunks.
// ---------------------------------------------------------------------------
__global__ void k_cvt_w(const float* __restrict__ src, float* __restrict__ dst, int nmat)
{
    int i = blockIdx.x * blockDim.x + threadIdx.x;
    if (i >= nmat * 16384) return;
    int m = i >> 14, rem = i & 16383;
    int k = rem >> 7, n = rem & 127;
    int kk = k & 31;
    int dpos = m * WMAT + (k >> 5) * WCHUNK
             + (((kk >> 3) * 4) + (kk & 3)) * SWROW + n * 2 + ((kk >> 2) & 1);
    dst[dpos] = __uint_as_float(f2tf32(src[i]));
}

__global__ void k_cvt_proj(const float* __restrict__ src, float* __restrict__ dst, int K)
{
    int i = blockIdx.x * blockDim.x + threadIdx.x;
    if (i >= K * 128) return;
    int k = i >> 7, n = i & 127;
    int kk = k & 31;
    int dpos = (k >> 5) * WCHUNK
             + (((kk >> 3) * 4) + (kk & 3)) * SWROW + n * 2 + ((kk >> 2) & 1);
    dst[dpos] = __uint_as_float(f2tf32(src[i]));
}

// ---------------------------------------------------------------------------
// CSR build
// ---------------------------------------------------------------------------
__global__ void k_count(const int* __restrict__ ei, int E, int* __restrict__ cnt)
{
    int i = blockIdx.x * blockDim.x + threadIdx.x;
    if (i < E) atomicAdd(cnt + __ldg(ei + E + i), 1);
}

__global__ void scan_block(int* __restrict__ data, int n, int* __restrict__ bsums)
{
    __shared__ int s[1024];
    int t = threadIdx.x;
    int i = blockIdx.x * 1024 + t;
    int v = (i < n) ? data[i] : 0;
    s[t] = v; __syncthreads();
    for (int d = 1; d < 1024; d <<= 1) {
        int x = (t >= d) ? s[t - d] : 0;
        __syncthreads();
        s[t] += x;
        __syncthreads();
    }
    if (i < n) data[i] = s[t] - v;
    if (t == 1023) bsums[blockIdx.x] = s[1023];
}

__global__ void scan_tops(int* __restrict__ bsums, int nb)
{
    __shared__ int s[128];
    int t = threadIdx.x;
    int v = (t < nb) ? bsums[t] : 0;
    s[t] = v; __syncthreads();
    for (int d = 1; d < 128; d <<= 1) {
        int x = (t >= d) ? s[t - d] : 0;
        __syncthreads();
        s[t] += x;
        __syncthreads();
    }
    if (t < nb) bsums[t] = s[t] - v;
}

__global__ void scan_add(int* __restrict__ data, int n,
                         const int* __restrict__ bsums, int total)
{
    int i = blockIdx.x * 1024 + threadIdx.x;
    if (i < n) data[i] += bsums[blockIdx.x];
    if (i == 0) data[n] = total;
}

__global__ void k_fill(const int* __restrict__ ei, int E,
                       int* __restrict__ cursor, int* __restrict__ csrsrc)
{
    int i = blockIdx.x * blockDim.x + threadIdx.x;
    if (i < E) {
        int d = __ldg(ei + E + i);
        int s = __ldg(ei + i);
        int p = atomicAdd(cursor + d, 1);
        csrsrc[p] = s;
    }
}

// ---------------------------------------------------------------------------
// aggr[i] = sum_e relu(A[i] + B[src_e]); writes PERMUTED tf32 rows.
// ---------------------------------------------------------------------------
__global__ void csr_agg(const int* __restrict__ rowptr, const int* __restrict__ csrsrc,
                        const float* __restrict__ A, const float* __restrict__ B,
                        float* __restrict__ aggr, int n)
{
    int w = (blockIdx.x * blockDim.x + threadIdx.x) >> 5;
    int lane = threadIdx.x & 31;
    if (w >= n) return;
    int s0 = __ldg(rowptr + w), s1 = __ldg(rowptr + w + 1);
    float4 a = *(const float4*)(A + (size_t)w * 128 + lane * 4);
    float4 acc0 = make_float4(0.f, 0.f, 0.f, 0.f);
    float4 acc1 = make_float4(0.f, 0.f, 0.f, 0.f);
    int e = s0;
    for (; e + 2 <= s1; e += 2) {
        int i0 = __ldg(csrsrc + e);
        int i1 = __ldg(csrsrc + e + 1);
        float4 b0 = *(const float4*)(B + (size_t)i0 * 128 + lane * 4);
        float4 b1 = *(const float4*)(B + (size_t)i1 * 128 + lane * 4);
        acc0.x += fmaxf(a.x + b0.x, 0.f); acc0.y += fmaxf(a.y + b0.y, 0.f);
        acc0.z += fmaxf(a.z + b0.z, 0.f); acc0.w += fmaxf(a.w + b0.w, 0.f);
        acc1.x += fmaxf(a.x + b1.x, 0.f); acc1.y += fmaxf(a.y + b1.y, 0.f);
        acc1.z += fmaxf(a.z + b1.z, 0.f); acc1.w += fmaxf(a.w + b1.w, 0.f);
    }
    if (e < s1) {
        int s = __ldg(csrsrc + e);
        float4 b = *(const float4*)(B + (size_t)s * 128 + lane * 4);
        acc0.x += fmaxf(a.x + b.x, 0.f); acc0.y += fmaxf(a.y + b.y, 0.f);
        acc0.z += fmaxf(a.z + b.z, 0.f); acc0.w += fmaxf(a.w + b.w, 0.f);
    }
    float o[4];
    o[0] = __uint_as_float(f2tf32(acc0.x + acc1.x));
    o[1] = __uint_as_float(f2tf32(acc0.y + acc1.y));
    o[2] = __uint_as_float(f2tf32(acc0.z + acc1.z));
    o[3] = __uint_as_float(f2tf32(acc0.w + acc1.w));
    float* dst = aggr + (size_t)w * 128;
#pragma unroll
    for (int j = 0; j < 4; j++) {
        int cc = lane * 4 + j;
        dst[kperm(cc)] = o[j];
    }
}

// ---------------------------------------------------------------------------
__global__ void pool_cnt(const int* __restrict__ batch, int n, float* __restrict__ cnt)
{
    int i = blockIdx.x * blockDim.x + threadIdx.x;
    if (i < n) atomicAdd(cnt + __ldg(batch + i), 1.0f);
}

__global__ void pool_div(const float* __restrict__ sums, const float* __restrict__ cnt,
                         float* __restrict__ fused, int colofs)
{
    int g = blockIdx.x, c = threadIdx.x;
    float cc = fmaxf(cnt[g], 1.0f);
    fused[(size_t)g * 256 + colofs + c] = sums[(size_t)g * 128 + c] / cc;
}

__global__ void head_kernel(const float* __restrict__ fused,
                            const float* __restrict__ mu_w, const float* __restrict__ mu_b,
                            const float* __restrict__ lv_w, const float* __restrict__ lv_b,
                            float* __restrict__ mu_out, float* __restrict__ lv_out)
{
    __shared__ float sf[256];
    int g = blockIdx.x, t = threadIdx.x;
    sf[t]       = fused[(size_t)g * 256 + t];
    sf[t + 128] = fused[(size_t)g * 256 + 128 + t];
    __syncthreads();
    if (t < 112) {
        bool is_mu = (t < 56);
        int j = is_mu ? t : t - 56;
        const float* Wp = is_mu ? mu_w : lv_w;
        float acc = is_mu ? mu_b[j] : lv_b[j];
#pragma unroll 8
        for (int k = 0; k < 256; k++) acc += sf[k] * Wp[k * ZD + j];
        if (is_mu) mu_out[(size_t)g * ZD + j] = acc;
        else       lv_out[(size_t)g * ZD + j] = acc;
    }
}

// ---------------------------------------------------------------------------
struct Scratch {
    float *A, *B, *aggr, *sums, *cnt, *wt;
    int *rowptr, *cursor, *csrsrc, *bsums;
};

static void csr_build(cudaStream_t st, const Scratch& S, const int* ei, int E, int n)
{
    int nb  = (n + 1023) / 1024;
    int ebk = (E + 255) / 256;
    cudaMemsetAsync(S.rowptr, 0, (size_t)(n + 1) * sizeof(int), st);
    k_count<<<ebk, 256, 0, st>>>(ei, E, S.rowptr);
    scan_block<<<nb, 1024, 0, st>>>(S.rowptr, n, S.bsums);
    scan_tops<<<1, 128, 0, st>>>(S.bsums, nb);
    scan_add<<<nb, 1024, 0, st>>>(S.rowptr, n, S.bsums, E);
    cudaMemcpyAsync(S.cursor, S.rowptr, (size_t)n * sizeof(int),
                    cudaMemcpyDeviceToDevice, st);
    k_fill<<<ebk, 256, 0, st>>>(ei, E, S.cursor, S.csrsrc);
}

static void encode_main(cudaStream_t st, const Scratch& S,
                        const float* x, int n, int din,
                        const int* batch, const float* pw, const float* pb,
                        const float* mw, const float* mb,
                        const float* lw, const float* lb,
                        float* fused, int colofs, cudaEvent_t ev_csr)
{
    int gb  = (n + 127) / 128;
    int wbk = (int)(((long long)n * 32 + 255) / 256);

    // permuted tf32 weight scratch: proj | msg(6 mats) | lin(3 mats)
    const int proj_words = (din / 32) * WCHUNK;
    float* wproj = S.wt;
    float* wmsg  = S.wt + proj_words;
    float* wlin  = wmsg + 6 * WMAT;
    k_cvt_proj<<<(din * 128 + 255) / 256, 256, 0, st>>>(pw, wproj, din);
    k_cvt_w<<<(6 * 16384 + 255) / 256, 256, 0, st>>>(mw, wmsg, 6);
    k_cvt_w<<<(3 * 16384 + 255) / 256, 256, 0, st>>>(lw, wlin, 3);

    fused_layer<<<gb, 256, 0, st>>>(x, din, n, 1, wproj, pb,
                                    wmsg, mb, wmsg + WMAT, S.A, S.B);
    if (ev_csr) cudaStreamWaitEvent(st, ev_csr, 0);
    csr_agg<<<wbk, 256, 0, st>>>(S.rowptr, S.csrsrc, S.A, S.B, S.aggr, n);

    for (int l = 1; l < 3; l++) {
        fused_layer<<<gb, 256, 0, st>>>(S.aggr, 128, n, 0,
                                        wlin + (size_t)(l - 1) * WMAT, lb + (l - 1) * 128,
                                        wmsg + (size_t)(2 * l) * WMAT, mb + l * 128,
                                        wmsg + (size_t)(2 * l + 1) * WMAT, S.A, S.B);
        csr_agg<<<wbk, 256, 0, st>>>(S.rowptr, S.csrsrc, S.A, S.B, S.aggr, n);
    }

    cudaMemsetAsync(S.sums, 0, (size_t)NGRAPHS * 128 * sizeof(float), st);
    gemm_pool<<<gb, 256, 0, st>>>(S.aggr, wlin + (size_t)2 * WMAT, lb + 2 * 128,
                                  n, batch, S.sums);
    cudaMemsetAsync(S.cnt, 0, (size_t)NGRAPHS * sizeof(float), st);
    pool_cnt<<<(n + 255) / 256, 256, 0, st>>>(batch, n, S.cnt);
    pool_div<<<NGRAPHS, 128, 0, st>>>(S.sums, S.cnt, fused, colofs);
}

extern "C" void kernel_launch(void* const* d_in, const int* in_sizes, int n_in,
                              void* d_out, int out_size)
{
    const float* tree_x      = (const float*)d_in[0];
    const int*   tree_ei     = (const int*)  d_in[1];
    const float* graph_x     = (const float*)d_in[2];
    const int*   graph_ei    = (const int*)  d_in[3];
    const int*   batch_tree  = (const int*)  d_in[4];
    const int*   batch_graph = (const int*)  d_in[5];
    const float* t_proj_w = (const float*)d_in[6];
    const float* t_proj_b = (const float*)d_in[7];
    const float* t_msg_w  = (const float*)d_in[8];
    const float* t_msg_b  = (const float*)d_in[9];
    const float* t_lin_w  = (const float*)d_in[10];
    const float* t_lin_b  = (const float*)d_in[11];
    const float* gr_proj_w = (const float*)d_in[12];
    const float* gr_proj_b = (const float*)d_in[13];
    const float* gr_msg_w  = (const float*)d_in[14];
    const float* gr_msg_b  = (const float*)d_in[15];
    const float* gr_lin_w  = (const float*)d_in[16];
    const float* gr_lin_b  = (const float*)d_in[17];
    const float* mu_w = (const float*)d_in[18];
    const float* mu_b = (const float*)d_in[19];
    const float* lv_w = (const float*)d_in[20];
    const float* lv_b = (const float*)d_in[21];
    float* out = (float*)d_out;

    const int n_tree  = in_sizes[0] / 64;
    const int e_tree  = in_sizes[1] / 2;
    const int n_graph = in_sizes[2] / 32;
    const int e_graph = in_sizes[3] / 2;

    Scratch G, T;
    cudaGetSymbolAddress((void**)&G.A,      g_A);
    cudaGetSymbolAddress((void**)&G.B,      g_B);
    cudaGetSymbolAddress((void**)&G.aggr,   g_aggr);
    cudaGetSymbolAddress((void**)&G.sums,   g_sums);
    cudaGetSymbolAddress((void**)&G.cnt,    g_cnt);
    cudaGetSymbolAddress((void**)&G.wt,     g_wt);
    cudaGetSymbolAddress((void**)&G.rowptr, g_rowptr);
    cudaGetSymbolAddress((void**)&G.cursor, g_cursor);
    cudaGetSymbolAddress((void**)&G.csrsrc, g_csrsrc);
    cudaGetSymbolAddress((void**)&G.bsums,  g_bsums);
    cudaGetSymbolAddress((void**)&T.A,      t_A);
    cudaGetSymbolAddress((void**)&T.B,      t_B);
    cudaGetSymbolAddress((void**)&T.aggr,   t_aggr);
    cudaGetSymbolAddress((void**)&T.sums,   t_sums);
    cudaGetSymbolAddress((void**)&T.cnt,    t_cnt);
    cudaGetSymbolAddress((void**)&T.wt,     t_wt);
    cudaGetSymbolAddress((void**)&T.rowptr, t_rowptr);
    cudaGetSymbolAddress((void**)&T.cursor, t_cursor);
    cudaGetSymbolAddress((void**)&T.csrsrc, t_csrsrc);
    cudaGetSymbolAddress((void**)&T.bsums,  t_bsums);

    static cudaStream_t s_tree = nullptr, s_csr = nullptr;
    static cudaEvent_t ev_fork = nullptr, ev_join = nullptr, ev_csr = nullptr;
    if (!s_tree) {
        cudaStreamCreateWithFlags(&s_tree, cudaStreamNonBlocking);
        cudaStreamCreateWithFlags(&s_csr, cudaStreamNonBlocking);
        cudaEventCreateWithFlags(&ev_fork, cudaEventDisableTiming);
        cudaEventCreateWithFlags(&ev_join, cudaEventDisableTiming);
        cudaEventCreateWithFlags(&ev_csr, cudaEventDisableTiming);
    }

    float* fused = out + 2 * NGRAPHS * ZD;   // output layout: mu | logvar | fused

    cudaEventRecord(ev_fork, 0);
    cudaStreamWaitEvent(s_tree, ev_fork, 0);
    cudaStreamWaitEvent(s_csr, ev_fork, 0);

    csr_build(s_tree, T, tree_ei, e_tree, n_tree);
    encode_main(s_tree, T, tree_x, n_tree, 64, batch_tree,
                t_proj_w, t_proj_b, t_msg_w, t_msg_b, t_lin_w, t_lin_b,
                fused, 0, nullptr);

    csr_build(s_csr, G, graph_ei, e_graph, n_graph);
    cudaEventRecord(ev_csr, s_csr);
    encode_main(0, G, graph_x, n_graph, 32, batch_graph,
                gr_proj_w, gr_proj_b, gr_msg_w, gr_msg_b, gr_lin_w, gr_lin_b,
                fused, 128, ev_csr);

    cudaEventRecord(ev_join, s_tree);
    cudaStreamWaitEvent(0, ev_join, 0);

    head_kernel<<<NGRAPHS, 128>>>(fused, mu_w, mu_b, lv_w, lv_b,
                                  out, out + NGRAPHS * ZD);
}

// round 10
// speedup vs baseline: 1.2759x; 1.2759x over previous
#include <cuda_runtime.h>
#include <cuda_fp16.h>
#include <cstdint>

#define NGRAPHS 1024
#define ZD 56

// ---- graph-encoder scratch ----
__device__ float g_A   [100000 * 128];
__device__ float g_B   [100000 * 128];
__device__ float g_aggr[100000 * 64];     // fp16 rows (128 halves)
__device__ float g_sums[NGRAPHS * 128];
__device__ float g_cnt [NGRAPHS];
__device__ int   g_rowptr[100001];
__device__ int   g_cursor[100001];
__device__ int   g_csrsrc[400000];
__device__ int   g_bsums[128];
__device__ float g_wt  [120000];          // fp16 chunks (as float storage)
// ---- tree-encoder scratch ----
__device__ float t_A   [20000 * 128];
__device__ float t_B   [20000 * 128];
__device__ float t_aggr[20000 * 64];
__device__ float t_sums[NGRAPHS * 128];
__device__ float t_cnt [NGRAPHS];
__device__ int   t_rowptr[20001];
__device__ int   t_cursor[20001];
__device__ int   t_csrsrc[40000];
__device__ int   t_bsums[128];
__device__ float t_wt  [120000];

#define HSTR 136                  // halves per sH row (272 B)
#define BSTR 40                   // halves per weight-chunk row (80 B, 32 used)
#define CHUNKH (128 * BSTR)       // 5120 halves per 32-k chunk
#define MATH   (4 * CHUNKH)       // halves per 128x128 matrix

__device__ __forceinline__ uint32_t smem_u32(const void* p) {
    return (uint32_t)__cvta_generic_to_shared(p);
}
__device__ __forceinline__ void cp16(uint32_t dst, const void* src) {
    asm volatile("cp.async.cg.shared.global [%0], [%1], 16;" :: "r"(dst), "l"(src));
}
__device__ __forceinline__ void cp16z(uint32_t dst, const void* src, int srcsz) {
    asm volatile("cp.async.cg.shared.global [%0], [%1], 16, %2;"
                 :: "r"(dst), "l"(src), "r"(srcsz));
}
#define CP_COMMIT() asm volatile("cp.async.commit_group;")
template<int N> __device__ __forceinline__ void cp_wait() {
    asm volatile("cp.async.wait_group %0;" :: "n"(N));
}

// fp16 m16n8k16 MMAs over one 32-k chunk. sH: stride HSTR halves, chunk at
// half-offset hk0. sW: one [128n][BSTR] chunk. Warp tile 32x64 (2x8 frags).
__device__ __forceinline__ void mma_chunk(float c[2][8][4],
                                          const __half* __restrict__ sH, int hk0,
                                          const __half* __restrict__ sW,
                                          int wm, int wn, int g, int tg)
{
#pragma unroll
    for (int kk = 0; kk < 2; kk++) {
        uint32_t a[2][4], b[8][2];
#pragma unroll
        for (int mi = 0; mi < 2; mi++) {
            int base = (wm + mi * 16 + g) * HSTR + hk0 + kk * 16 + tg * 2;
            a[mi][0] = *(const uint32_t*)&sH[base];
            a[mi][1] = *(const uint32_t*)&sH[base + 8 * HSTR];
            a[mi][2] = *(const uint32_t*)&sH[base + 8];
            a[mi][3] = *(const uint32_t*)&sH[base + 8 * HSTR + 8];
        }
#pragma unroll
        for (int ni = 0; ni < 8; ni++) {
            int wb = (wn + ni * 8 + g) * BSTR + kk * 16 + tg * 2;
            b[ni][0] = *(const uint32_t*)&sW[wb];
            b[ni][1] = *(const uint32_t*)&sW[wb + 8];
        }
#pragma unroll
        for (int mi = 0; mi < 2; mi++)
#pragma unroll
            for (int ni = 0; ni < 8; ni++) {
                asm volatile(
                    "mma.sync.aligned.m16n8k16.row.col.f32.f16.f16.f32 "
                    "{%0,%1,%2,%3},{%4,%5,%6,%7},{%8,%9},{%0,%1,%2,%3};"
                    : "+f"(c[mi][ni][0]), "+f"(c[mi][ni][1]),
                      "+f"(c[mi][ni][2]), "+f"(c[mi][ni][3])
                    : "r"(a[mi][0]), "r"(a[mi][1]), "r"(a[mi][2]), "r"(a[mi][3]),
                      "r"(b[ni][0]), "r"(b[ni][1]));
            }
    }
}

// ---------------------------------------------------------------------------
// Fused node update: h = relu(X@Wmain+b) in smem (fp16); A = h@Wtop+bt; B = h@Wbot
// ---------------------------------------------------------------------------
__global__ __launch_bounds__(256, 2)
void fused_layer(const void* __restrict__ Xv, int K, int M, int xcvt,
                 const __half* __restrict__ Wmain, const float* __restrict__ bmain,
                 const __half* __restrict__ Wtop,  const float* __restrict__ btop,
                 const __half* __restrict__ Wbot,
                 float* __restrict__ Aout, float* __restrict__ Bout)
{
    __shared__ __half sH[128 * HSTR];
    __shared__ __half sW[2][CHUNKH];
    const int tid  = threadIdx.x;
    const int warp = tid >> 5, lane = tid & 31;
    const int g  = lane >> 2;
    const int tg = lane & 3;
    const int wm = (warp >> 1) * 32;
    const int wn = (warp & 1) * 64;
    const int row0 = blockIdx.x * 128;

    const int n1 = K >> 5;
    const int total = n1 + 8;

    auto wsrc = [&](int i) -> const __half* {
        if (i < n1) return Wmain + (size_t)i * CHUNKH;
        int j = i - n1;
        return (j < 4) ? (Wtop + (size_t)j * CHUNKH) : (Wbot + (size_t)(j - 4) * CHUNKH);
    };
    auto issue_w = [&](int i, int buf) {
        const char* src = (const char*)wsrc(i);
        uint32_t base = smem_u32(&sW[buf][0]);
        for (int s = tid; s < CHUNKH / 8; s += 256)      // 640 16B units
            cp16(base + (uint32_t)s * 16, src + s * 16);
    };

    if (!xcvt) {   // X = fp16 aggr rows (128 halves): raw async copy
        uint32_t base = smem_u32(sH);
        const char* xh = (const char*)Xv;
        for (int s = tid; s < 128 * 16; s += 256) {
            int row = s >> 4, u = s & 15;
            cp16z(base + (uint32_t)(row * (HSTR * 2) + u * 16),
                  xh + (size_t)(row0 + row) * 256 + u * 16,
                  (row0 + row < M) ? 16 : 0);
        }
    }
    issue_w(0, 0); CP_COMMIT();
    issue_w(1, 1); CP_COMMIT();
    if (xcvt) {    // layer 0: raw fp32 input, convert to fp16 (K = 32 or 64)
        const float* X = (const float*)Xv;
        for (int i = tid; i < 128 * K; i += 256) {
            int r = (K == 32) ? (i >> 5) : (i >> 6);
            int k = i & (K - 1);
            int row = row0 + r;
            float v = (row < M) ? X[(size_t)row * K + k] : 0.0f;
            sH[r * HSTR + k] = __float2half_rn(v);
        }
    }

    float c[2][8][4];
#pragma unroll
    for (int mi = 0; mi < 2; mi++)
#pragma unroll
        for (int ni = 0; ni < 8; ni++)
#pragma unroll
            for (int q = 0; q < 4; q++) c[mi][ni][q] = 0.0f;

    for (int i = 0; i < total; i++) {
        if (i + 2 < total) cp_wait<1>(); else cp_wait<0>();
        __syncthreads();
        int hk0 = ((i < n1) ? i : ((i - n1) & 3)) * 32;
        mma_chunk(c, sH, hk0, &sW[i & 1][0], wm, wn, g, tg);
        __syncthreads();
        if (i + 2 < total) { issue_w(i + 2, i & 1); CP_COMMIT(); }

        if (i == n1 - 1) {
            // h = relu(c + bmain) -> sH (fp16); reset c
#pragma unroll
            for (int mi = 0; mi < 2; mi++)
#pragma unroll
                for (int half = 0; half < 2; half++) {
                    int r = wm + mi * 16 + g + half * 8;
#pragma unroll
                    for (int ni = 0; ni < 8; ni++) {
                        int col = wn + ni * 8 + tg * 2;
                        float vx = fmaxf(c[mi][ni][half * 2 + 0] + bmain[col],     0.f);
                        float vy = fmaxf(c[mi][ni][half * 2 + 1] + bmain[col + 1], 0.f);
                        *(__half2*)&sH[r * HSTR + col] = __floats2half2_rn(vx, vy);
                    }
                }
#pragma unroll
            for (int mi = 0; mi < 2; mi++)
#pragma unroll
                for (int ni = 0; ni < 8; ni++)
#pragma unroll
                    for (int q = 0; q < 4; q++) c[mi][ni][q] = 0.0f;
        } else if (i == n1 + 3) {
            // A = c + btop (fp32); reset c
#pragma unroll
            for (int mi = 0; mi < 2; mi++)
#pragma unroll
                for (int half = 0; half < 2; half++) {
                    int row = row0 + wm + mi * 16 + g + half * 8;
                    if (row < M) {
#pragma unroll
                        for (int ni = 0; ni < 8; ni++) {
                            int col = wn + ni * 8 + tg * 2;
                            float2 o;
                            o.x = c[mi][ni][half * 2 + 0] + btop[col];
                            o.y = c[mi][ni][half * 2 + 1] + btop[col + 1];
                            *(float2*)(Aout + (size_t)row * 128 + col) = o;
                        }
                    }
                }
#pragma unroll
            for (int mi = 0; mi < 2; mi++)
#pragma unroll
                for (int ni = 0; ni < 8; ni++)
#pragma unroll
                    for (int q = 0; q < 4; q++) c[mi][ni][q] = 0.0f;
        } else if (i == total - 1) {
            // B = c (fp32)
#pragma unroll
            for (int mi = 0; mi < 2; mi++)
#pragma unroll
                for (int half = 0; half < 2; half++) {
                    int row = row0 + wm + mi * 16 + g + half * 8;
                    if (row < M) {
#pragma unroll
                        for (int ni = 0; ni < 8; ni++) {
                            int col = wn + ni * 8 + tg * 2;
                            float2 o;
                            o.x = c[mi][ni][half * 2 + 0];
                            o.y = c[mi][ni][half * 2 + 1];
                            *(float2*)(Bout + (size_t)row * 128 + col) = o;
                        }
                    }
                }
        }
    }
}

// ---------------------------------------------------------------------------
// Final-layer GEMM (fp16) + mean-pool numerator epilogue.
// ---------------------------------------------------------------------------
__global__ __launch_bounds__(256, 2)
void gemm_pool(const __half* __restrict__ Xh, const __half* __restrict__ W,
               const float* __restrict__ bias, int M,
               const int* __restrict__ batch, float* __restrict__ sums)
{
    __shared__ __half sH[128 * HSTR];
    __shared__ __half sW[4 * CHUNKH];
    const int tid  = threadIdx.x;
    const int warp = tid >> 5, lane = tid & 31;
    const int g  = lane >> 2;
    const int tg = lane & 3;
    const int wm = (warp >> 1) * 32;
    const int wn = (warp & 1) * 64;
    const int row0 = blockIdx.x * 128;

    {
        uint32_t xb = smem_u32(sH);
        const char* xs = (const char*)Xh;
        for (int s = tid; s < 128 * 16; s += 256) {
            int row = s >> 4, u = s & 15;
            cp16z(xb + (uint32_t)(row * (HSTR * 2) + u * 16),
                  xs + (size_t)(row0 + row) * 256 + u * 16,
                  (row0 + row < M) ? 16 : 0);
        }
        uint32_t wb = smem_u32(sW);
        const char* ws = (const char*)W;
        for (int s = tid; s < 4 * CHUNKH / 8; s += 256)
            cp16(wb + (uint32_t)s * 16, ws + s * 16);
    }
    CP_COMMIT();
    cp_wait<0>();
    __syncthreads();

    float c[2][8][4];
#pragma unroll
    for (int mi = 0; mi < 2; mi++)
#pragma unroll
        for (int ni = 0; ni < 8; ni++)
#pragma unroll
            for (int q = 0; q < 4; q++) c[mi][ni][q] = 0.0f;

#pragma unroll
    for (int i = 0; i < 4; i++)
        mma_chunk(c, sH, i * 32, &sW[i * CHUNKH], wm, wn, g, tg);

#pragma unroll
    for (int mi = 0; mi < 2; mi++)
#pragma unroll
        for (int half = 0; half < 2; half++) {
            int row = row0 + wm + mi * 16 + g + half * 8;
            if (row < M) {
                int gsel = __ldg(batch + row);
#pragma unroll
                for (int ni = 0; ni < 8; ni++) {
                    int col = wn + ni * 8 + tg * 2;
                    float ox = fmaxf(c[mi][ni][half * 2 + 0] + bias[col],     0.f);
                    float oy = fmaxf(c[mi][ni][half * 2 + 1] + bias[col + 1], 0.f);
                    float* p = sums + (size_t)gsel * 128 + col;
                    asm volatile("red.global.add.v2.f32 [%0], {%1,%2};"
                                 :: "l"(p), "f"(ox), "f"(oy) : "memory");
                }
            }
        }
}

// ---------------------------------------------------------------------------
// Weight conversion: src[m][k][n] fp32 -> fp16 chunks, transposed [n][k],
// padded rows (BSTR halves), chunked by 32 k.
// ---------------------------------------------------------------------------
__global__ void k_cvt_w(const float* __restrict__ src, __half* __restrict__ dst, int nmat)
{
    int i = blockIdx.x * blockDim.x + threadIdx.x;
    if (i >= nmat * 16384) return;
    int m = i >> 14, rem = i & 16383;
    int k = rem >> 7, n = rem & 127;
    dst[(size_t)m * MATH + (k >> 5) * CHUNKH + n * BSTR + (k & 31)] =
        __float2half_rn(src[i]);
}

__global__ void k_cvt_proj(const float* __restrict__ src, __half* __restrict__ dst, int K)
{
    int i = blockIdx.x * blockDim.x + threadIdx.x;
    if (i >= K * 128) return;
    int k = i >> 7, n = i & 127;
    dst[(k >> 5) * CHUNKH + n * BSTR + (k & 31)] = __float2half_rn(src[i]);
}

// ---------------------------------------------------------------------------
// CSR build
// ---------------------------------------------------------------------------
__global__ void k_count(const int* __restrict__ ei, int E, int* __restrict__ cnt)
{
    int i = blockIdx.x * blockDim.x + threadIdx.x;
    if (i < E) atomicAdd(cnt + __ldg(ei + E + i), 1);
}

__global__ void scan_block(int* __restrict__ data, int n, int* __restrict__ bsums)
{
    __shared__ int s[1024];
    int t = threadIdx.x;
    int i = blockIdx.x * 1024 + t;
    int v = (i < n) ? data[i] : 0;
    s[t] = v; __syncthreads();
    for (int d = 1; d < 1024; d <<= 1) {
        int x = (t >= d) ? s[t - d] : 0;
        __syncthreads();
        s[t] += x;
        __syncthreads();
    }
    if (i < n) data[i] = s[t] - v;
    if (t == 1023) bsums[blockIdx.x] = s[1023];
}

__global__ void scan_tops(int* __restrict__ bsums, int nb)
{
    __shared__ int s[128];
    int t = threadIdx.x;
    int v = (t < nb) ? bsums[t] : 0;
    s[t] = v; __syncthreads();
    for (int d = 1; d < 128; d <<= 1) {
        int x = (t >= d) ? s[t - d] : 0;
        __syncthreads();
        s[t] += x;
        __syncthreads();
    }
    if (t < nb) bsums[t] = s[t] - v;
}

__global__ void scan_add(int* __restrict__ data, int n,
                         const int* __restrict__ bsums, int total)
{
    int i = blockIdx.x * 1024 + threadIdx.x;
    if (i < n) data[i] += bsums[blockIdx.x];
    if (i == 0) data[n] = total;
}

__global__ void k_fill(const int* __restrict__ ei, int E,
                       int* __restrict__ cursor, int* __restrict__ csrsrc)
{
    int i = blockIdx.x * blockDim.x + threadIdx.x;
    if (i < E) {
        int d = __ldg(ei + E + i);
        int s = __ldg(ei + i);
        int p = atomicAdd(cursor + d, 1);
        csrsrc[p] = s;
    }
}

// ---------------------------------------------------------------------------
// aggr[i] = sum_e relu(A[i] + B[src_e]); output fp16 rows (128 halves).
// ---------------------------------------------------------------------------
__global__ void csr_agg(const int* __restrict__ rowptr, const int* __restrict__ csrsrc,
                        const float* __restrict__ A, const float* __restrict__ B,
                        __half* __restrict__ aggr, int n)
{
    int w = (blockIdx.x * blockDim.x + threadIdx.x) >> 5;
    int lane = threadIdx.x & 31;
    if (w >= n) return;
    int s0 = __ldg(rowptr + w), s1 = __ldg(rowptr + w + 1);
    float4 a = *(const float4*)(A + (size_t)w * 128 + lane * 4);
    float4 acc0 = make_float4(0.f, 0.f, 0.f, 0.f);
    float4 acc1 = make_float4(0.f, 0.f, 0.f, 0.f);
    int e = s0;
    for (; e + 2 <= s1; e += 2) {
        int i0 = __ldg(csrsrc + e);
        int i1 = __ldg(csrsrc + e + 1);
        float4 b0 = *(const float4*)(B + (size_t)i0 * 128 + lane * 4);
        float4 b1 = *(const float4*)(B + (size_t)i1 * 128 + lane * 4);
        acc0.x += fmaxf(a.x + b0.x, 0.f); acc0.y += fmaxf(a.y + b0.y, 0.f);
        acc0.z += fmaxf(a.z + b0.z, 0.f); acc0.w += fmaxf(a.w + b0.w, 0.f);
        acc1.x += fmaxf(a.x + b1.x, 0.f); acc1.y += fmaxf(a.y + b1.y, 0.f);
        acc1.z += fmaxf(a.z + b1.z, 0.f); acc1.w += fmaxf(a.w + b1.w, 0.f);
    }
    if (e < s1) {
        int s = __ldg(csrsrc + e);
        float4 b = *(const float4*)(B + (size_t)s * 128 + lane * 4);
        acc0.x += fmaxf(a.x + b.x, 0.f); acc0.y += fmaxf(a.y + b.y, 0.f);
        acc0.z += fmaxf(a.z + b.z, 0.f); acc0.w += fmaxf(a.w + b.w, 0.f);
    }
    __half2 h0 = __floats2half2_rn(acc0.x + acc1.x, acc0.y + acc1.y);
    __half2 h1 = __floats2half2_rn(acc0.z + acc1.z, acc0.w + acc1.w);
    uint2 o;
    o.x = *(uint32_t*)&h0;
    o.y = *(uint32_t*)&h1;
    *(uint2*)(aggr + (size_t)w * 128 + lane * 4) = o;
}

// ---------------------------------------------------------------------------
__global__ void pool_cnt(const int* __restrict__ batch, int n, float* __restrict__ cnt)
{
    int i = blockIdx.x * blockDim.x + threadIdx.x;
    if (i < n) atomicAdd(cnt + __ldg(batch + i), 1.0f);
}

__global__ void pool_div(const float* __restrict__ sums, const float* __restrict__ cnt,
                         float* __restrict__ fused, int colofs)
{
    int g = blockIdx.x, c = threadIdx.x;
    float cc = fmaxf(cnt[g], 1.0f);
    fused[(size_t)g * 256 + colofs + c] = sums[(size_t)g * 128 + c] / cc;
}

__global__ void head_kernel(const float* __restrict__ fused,
                            const float* __restrict__ mu_w, const float* __restrict__ mu_b,
                            const float* __restrict__ lv_w, const float* __restrict__ lv_b,
                            float* __restrict__ mu_out, float* __restrict__ lv_out)
{
    __shared__ float sf[256];
    int g = blockIdx.x, t = threadIdx.x;
    sf[t]       = fused[(size_t)g * 256 + t];
    sf[t + 128] = fused[(size_t)g * 256 + 128 + t];
    __syncthreads();
    if (t < 112) {
        bool is_mu = (t < 56);
        int j = is_mu ? t : t - 56;
        const float* Wp = is_mu ? mu_w : lv_w;
        float acc = is_mu ? mu_b[j] : lv_b[j];
#pragma unroll 8
        for (int k = 0; k < 256; k++) acc += sf[k] * Wp[k * ZD + j];
        if (is_mu) mu_out[(size_t)g * ZD + j] = acc;
        else       lv_out[(size_t)g * ZD + j] = acc;
    }
}

// ---------------------------------------------------------------------------
struct Scratch {
    float *A, *B, *sums, *cnt;
    __half *aggr, *wt;
    int *rowptr, *cursor, *csrsrc, *bsums;
};

static void csr_build(cudaStream_t st, const Scratch& S, const int* ei, int E, int n)
{
    int nb  = (n + 1023) / 1024;
    int ebk = (E + 255) / 256;
    cudaMemsetAsync(S.rowptr, 0, (size_t)(n + 1) * sizeof(int), st);
    k_count<<<ebk, 256, 0, st>>>(ei, E, S.rowptr);
    scan_block<<<nb, 1024, 0, st>>>(S.rowptr, n, S.bsums);
    scan_tops<<<1, 128, 0, st>>>(S.bsums, nb);
    scan_add<<<nb, 1024, 0, st>>>(S.rowptr, n, S.bsums, E);
    cudaMemcpyAsync(S.cursor, S.rowptr, (size_t)n * sizeof(int),
                    cudaMemcpyDeviceToDevice, st);
    k_fill<<<ebk, 256, 0, st>>>(ei, E, S.cursor, S.csrsrc);
}

static void encode_main(cudaStream_t st, const Scratch& S,
                        const float* x, int n, int din,
                        const int* batch, const float* pw, const float* pb,
                        const float* mw, const float* mb,
                        const float* lw, const float* lb,
                        float* fused, int colofs, cudaEvent_t ev_csr)
{
    int gb  = (n + 127) / 128;
    int wbk = (int)(((long long)n * 32 + 255) / 256);

    __half* wproj = S.wt;
    __half* wmsg  = S.wt + (size_t)(din / 32) * CHUNKH;
    __half* wlin  = wmsg + (size_t)6 * MATH;
    k_cvt_proj<<<(din * 128 + 255) / 256, 256, 0, st>>>(pw, wproj, din);
    k_cvt_w<<<(6 * 16384 + 255) / 256, 256, 0, st>>>(mw, wmsg, 6);
    k_cvt_w<<<(3 * 16384 + 255) / 256, 256, 0, st>>>(lw, wlin, 3);

    fused_layer<<<gb, 256, 0, st>>>(x, din, n, 1, wproj, pb,
                                    wmsg, mb, wmsg + MATH, S.A, S.B);
    if (ev_csr) cudaStreamWaitEvent(st, ev_csr, 0);
    csr_agg<<<wbk, 256, 0, st>>>(S.rowptr, S.csrsrc, S.A, S.B, S.aggr, n);

    for (int l = 1; l < 3; l++) {
        fused_layer<<<gb, 256, 0, st>>>(S.aggr, 128, n, 0,
                                        wlin + (size_t)(l - 1) * MATH, lb + (l - 1) * 128,
                                        wmsg + (size_t)(2 * l) * MATH, mb + l * 128,
                                        wmsg + (size_t)(2 * l + 1) * MATH, S.A, S.B);
        csr_agg<<<wbk, 256, 0, st>>>(S.rowptr, S.csrsrc, S.A, S.B, S.aggr, n);
    }

    cudaMemsetAsync(S.sums, 0, (size_t)NGRAPHS * 128 * sizeof(float), st);
    gemm_pool<<<gb, 256, 0, st>>>(S.aggr, wlin + (size_t)2 * MATH, lb + 2 * 128,
                                  n, batch, S.sums);
    cudaMemsetAsync(S.cnt, 0, (size_t)NGRAPHS * sizeof(float), st);
    pool_cnt<<<(n + 255) / 256, 256, 0, st>>>(batch, n, S.cnt);
    pool_div<<<NGRAPHS, 128, 0, st>>>(S.sums, S.cnt, fused, colofs);
}

extern "C" void kernel_launch(void* const* d_in, const int* in_sizes, int n_in,
                              void* d_out, int out_size)
{
    const float* tree_x      = (const float*)d_in[0];
    const int*   tree_ei     = (const int*)  d_in[1];
    const float* graph_x     = (const float*)d_in[2];
    const int*   graph_ei    = (const int*)  d_in[3];
    const int*   batch_tree  = (const int*)  d_in[4];
    const int*   batch_graph = (const int*)  d_in[5];
    const float* t_proj_w = (const float*)d_in[6];
    const float* t_proj_b = (const float*)d_in[7];
    const float* t_msg_w  = (const float*)d_in[8];
    const float* t_msg_b  = (const float*)d_in[9];
    const float* t_lin_w  = (const float*)d_in[10];
    const float* t_lin_b  = (const float*)d_in[11];
    const float* gr_proj_w = (const float*)d_in[12];
    const float* gr_proj_b = (const float*)d_in[13];
    const float* gr_msg_w  = (const float*)d_in[14];
    const float* gr_msg_b  = (const float*)d_in[15];
    const float* gr_lin_w  = (const float*)d_in[16];
    const float* gr_lin_b  = (const float*)d_in[17];
    const float* mu_w = (const float*)d_in[18];
    const float* mu_b = (const float*)d_in[19];
    const float* lv_w = (const float*)d_in[20];
    const float* lv_b = (const float*)d_in[21];
    float* out = (float*)d_out;

    const int n_tree  = in_sizes[0] / 64;
    const int e_tree  = in_sizes[1] / 2;
    const int n_graph = in_sizes[2] / 32;
    const int e_graph = in_sizes[3] / 2;

    Scratch G, T;
    cudaGetSymbolAddress((void**)&G.A,      g_A);
    cudaGetSymbolAddress((void**)&G.B,      g_B);
    cudaGetSymbolAddress((void**)&G.aggr,   g_aggr);
    cudaGetSymbolAddress((void**)&G.sums,   g_sums);
    cudaGetSymbolAddress((void**)&G.cnt,    g_cnt);
    cudaGetSymbolAddress((void**)&G.wt,     g_wt);
    cudaGetSymbolAddress((void**)&G.rowptr, g_rowptr);
    cudaGetSymbolAddress((void**)&G.cursor, g_cursor);
    cudaGetSymbolAddress((void**)&G.csrsrc, g_csrsrc);
    cudaGetSymbolAddress((void**)&G.bsums,  g_bsums);
    cudaGetSymbolAddress((void**)&T.A,      t_A);
    cudaGetSymbolAddress((void**)&T.B,      t_B);
    cudaGetSymbolAddress((void**)&T.aggr,   t_aggr);
    cudaGetSymbolAddress((void**)&T.sums,   t_sums);
    cudaGetSymbolAddress((void**)&T.cnt,    t_cnt);
    cudaGetSymbolAddress((void**)&T.wt,     t_wt);
    cudaGetSymbolAddress((void**)&T.rowptr, t_rowptr);
    cudaGetSymbolAddress((void**)&T.cursor, t_cursor);
    cudaGetSymbolAddress((void**)&T.csrsrc, t_csrsrc);
    cudaGetSymbolAddress((void**)&T.bsums,  t_bsums);

    static cudaStream_t s_tree = nullptr, s_csr = nullptr;
    static cudaEvent_t ev_fork = nullptr, ev_join = nullptr, ev_csr = nullptr;
    if (!s_tree) {
        cudaStreamCreateWithFlags(&s_tree, cudaStreamNonBlocking);
        cudaStreamCreateWithFlags(&s_csr, cudaStreamNonBlocking);
        cudaEventCreateWithFlags(&ev_fork, cudaEventDisableTiming);
        cudaEventCreateWithFlags(&ev_join, cudaEventDisableTiming);
        cudaEventCreateWithFlags(&ev_csr, cudaEventDisableTiming);
    }

    float* fused = out + 2 * NGRAPHS * ZD;   // output layout: mu | logvar | fused

    cudaEventRecord(ev_fork, 0);
    cudaStreamWaitEvent(s_tree, ev_fork, 0);
    cudaStreamWaitEvent(s_csr, ev_fork, 0);

    csr_build(s_tree, T, tree_ei, e_tree, n_tree);
    encode_main(s_tree, T, tree_x, n_tree, 64, batch_tree,
                t_proj_w, t_proj_b, t_msg_w, t_msg_b, t_lin_w, t_lin_b,
                fused, 0, nullptr);

    csr_build(s_csr, G, graph_ei, e_graph, n_graph);
    cudaEventRecord(ev_csr, s_csr);
    encode_main(0, G, graph_x, n_graph, 32, batch_graph,
                gr_proj_w, gr_proj_b, gr_msg_w, gr_msg_b, gr_lin_w, gr_lin_b,
                fused, 128, ev_csr);

    cudaEventRecord(ev_join, s_tree);
    cudaStreamWaitEvent(0, ev_join, 0);

    head_kernel<<<NGRAPHS, 128>>>(fused, mu_w, mu_b, lv_w, lv_b,
                                  out, out + NGRAPHS * ZD);
}

// round 11
// speedup vs baseline: 1.5084x; 1.1822x over previous
#include <cuda_runtime.h>
#include <cuda_fp16.h>
#include <cstdint>

#define NGRAPHS 1024
#define ZD 56

// ---- graph-encoder scratch ----
__device__ __half g_A   [100000 * 128];
__device__ __half g_B   [100000 * 128];
__device__ __half g_aggr[100000 * 128];
__device__ float  g_sums[NGRAPHS * 128];
__device__ float  g_cnt [NGRAPHS];
__device__ int    g_rowptr[100001];
__device__ int    g_cursor[100001];
__device__ int    g_csrsrc[400000];
__device__ int    g_bsums[128];
__device__ __half g_wt  [240000];
// ---- tree-encoder scratch ----
__device__ __half t_A   [20000 * 128];
__device__ __half t_B   [20000 * 128];
__device__ __half t_aggr[20000 * 128];
__device__ float  t_sums[NGRAPHS * 128];
__device__ float  t_cnt [NGRAPHS];
__device__ int    t_rowptr[20001];
__device__ int    t_cursor[20001];
__device__ int    t_csrsrc[40000];
__device__ int    t_bsums[128];
__device__ __half t_wt  [240000];

#define HSTR 136                  // halves per sH row (272 B)
#define BSTR 40                   // halves per weight-chunk row (80 B, 32 used)
#define CHUNKH (128 * BSTR)       // 5120 halves per 32-k chunk
#define MATH   (4 * CHUNKH)       // halves per 128x128 matrix

__device__ __forceinline__ uint32_t smem_u32(const void* p) {
    return (uint32_t)__cvta_generic_to_shared(p);
}
__device__ __forceinline__ void cp16(uint32_t dst, const void* src) {
    asm volatile("cp.async.cg.shared.global [%0], [%1], 16;" :: "r"(dst), "l"(src));
}
__device__ __forceinline__ void cp16z(uint32_t dst, const void* src, int srcsz) {
    asm volatile("cp.async.cg.shared.global [%0], [%1], 16, %2;"
                 :: "r"(dst), "l"(src), "r"(srcsz));
}
#define CP_COMMIT() asm volatile("cp.async.commit_group;")
template<int N> __device__ __forceinline__ void cp_wait() {
    asm volatile("cp.async.wait_group %0;" :: "n"(N));
}

// fp16 m16n8k16 MMAs over one 32-k chunk.
__device__ __forceinline__ void mma_chunk(float c[2][8][4],
                                          const __half* __restrict__ sH, int hk0,
                                          const __half* __restrict__ sW,
                                          int wm, int wn, int g, int tg)
{
#pragma unroll
    for (int kk = 0; kk < 2; kk++) {
        uint32_t a[2][4], b[8][2];
#pragma unroll
        for (int mi = 0; mi < 2; mi++) {
            int base = (wm + mi * 16 + g) * HSTR + hk0 + kk * 16 + tg * 2;
            a[mi][0] = *(const uint32_t*)&sH[base];
            a[mi][1] = *(const uint32_t*)&sH[base + 8 * HSTR];
            a[mi][2] = *(const uint32_t*)&sH[base + 8];
            a[mi][3] = *(const uint32_t*)&sH[base + 8 * HSTR + 8];
        }
#pragma unroll
        for (int ni = 0; ni < 8; ni++) {
            int wb = (wn + ni * 8 + g) * BSTR + kk * 16 + tg * 2;
            b[ni][0] = *(const uint32_t*)&sW[wb];
            b[ni][1] = *(const uint32_t*)&sW[wb + 8];
        }
#pragma unroll
        for (int mi = 0; mi < 2; mi++)
#pragma unroll
            for (int ni = 0; ni < 8; ni++) {
                asm volatile(
                    "mma.sync.aligned.m16n8k16.row.col.f32.f16.f16.f32 "
                    "{%0,%1,%2,%3},{%4,%5,%6,%7},{%8,%9},{%0,%1,%2,%3};"
                    : "+f"(c[mi][ni][0]), "+f"(c[mi][ni][1]),
                      "+f"(c[mi][ni][2]), "+f"(c[mi][ni][3])
                    : "r"(a[mi][0]), "r"(a[mi][1]), "r"(a[mi][2]), "r"(a[mi][3]),
                      "r"(b[ni][0]), "r"(b[ni][1]));
            }
    }
}

// ---------------------------------------------------------------------------
// Fused node update: h = relu(X@Wmain+b) in smem (fp16); A = h@Wtop+bt; B = h@Wbot
// A/B outputs now fp16 rows (128 halves).
// ---------------------------------------------------------------------------
__global__ __launch_bounds__(256, 2)
void fused_layer(const void* __restrict__ Xv, int K, int M, int xcvt,
                 const __half* __restrict__ Wmain, const float* __restrict__ bmain,
                 const __half* __restrict__ Wtop,  const float* __restrict__ btop,
                 const __half* __restrict__ Wbot,
                 __half* __restrict__ Aout, __half* __restrict__ Bout)
{
    __shared__ __half sH[128 * HSTR];
    __shared__ __half sW[2][CHUNKH];
    const int tid  = threadIdx.x;
    const int warp = tid >> 5, lane = tid & 31;
    const int g  = lane >> 2;
    const int tg = lane & 3;
    const int wm = (warp >> 1) * 32;
    const int wn = (warp & 1) * 64;
    const int row0 = blockIdx.x * 128;

    const int n1 = K >> 5;
    const int total = n1 + 8;

    auto wsrc = [&](int i) -> const __half* {
        if (i < n1) return Wmain + (size_t)i * CHUNKH;
        int j = i - n1;
        return (j < 4) ? (Wtop + (size_t)j * CHUNKH) : (Wbot + (size_t)(j - 4) * CHUNKH);
    };
    auto issue_w = [&](int i, int buf) {
        const char* src = (const char*)wsrc(i);
        uint32_t base = smem_u32(&sW[buf][0]);
        for (int s = tid; s < CHUNKH / 8; s += 256)
            cp16(base + (uint32_t)s * 16, src + s * 16);
    };

    if (!xcvt) {   // X = fp16 aggr rows (128 halves): raw async copy
        uint32_t base = smem_u32(sH);
        const char* xh = (const char*)Xv;
        for (int s = tid; s < 128 * 16; s += 256) {
            int row = s >> 4, u = s & 15;
            cp16z(base + (uint32_t)(row * (HSTR * 2) + u * 16),
                  xh + (size_t)(row0 + row) * 256 + u * 16,
                  (row0 + row < M) ? 16 : 0);
        }
    }
    issue_w(0, 0); CP_COMMIT();
    issue_w(1, 1); CP_COMMIT();
    if (xcvt) {    // layer 0: raw fp32 input -> fp16 (K = 32 or 64)
        const float* X = (const float*)Xv;
        for (int i = tid; i < 128 * K; i += 256) {
            int r = (K == 32) ? (i >> 5) : (i >> 6);
            int k = i & (K - 1);
            int row = row0 + r;
            float v = (row < M) ? X[(size_t)row * K + k] : 0.0f;
            sH[r * HSTR + k] = __float2half_rn(v);
        }
    }

    float c[2][8][4];
#pragma unroll
    for (int mi = 0; mi < 2; mi++)
#pragma unroll
        for (int ni = 0; ni < 8; ni++)
#pragma unroll
            for (int q = 0; q < 4; q++) c[mi][ni][q] = 0.0f;

    for (int i = 0; i < total; i++) {
        if (i + 2 < total) cp_wait<1>(); else cp_wait<0>();
        __syncthreads();
        int hk0 = ((i < n1) ? i : ((i - n1) & 3)) * 32;
        mma_chunk(c, sH, hk0, &sW[i & 1][0], wm, wn, g, tg);
        __syncthreads();
        if (i + 2 < total) { issue_w(i + 2, i & 1); CP_COMMIT(); }

        if (i == n1 - 1) {
            // h = relu(c + bmain) -> sH (fp16); reset c
#pragma unroll
            for (int mi = 0; mi < 2; mi++)
#pragma unroll
                for (int half = 0; half < 2; half++) {
                    int r = wm + mi * 16 + g + half * 8;
#pragma unroll
                    for (int ni = 0; ni < 8; ni++) {
                        int col = wn + ni * 8 + tg * 2;
                        float vx = fmaxf(c[mi][ni][half * 2 + 0] + bmain[col],     0.f);
                        float vy = fmaxf(c[mi][ni][half * 2 + 1] + bmain[col + 1], 0.f);
                        *(__half2*)&sH[r * HSTR + col] = __floats2half2_rn(vx, vy);
                    }
                }
#pragma unroll
            for (int mi = 0; mi < 2; mi++)
#pragma unroll
                for (int ni = 0; ni < 8; ni++)
#pragma unroll
                    for (int q = 0; q < 4; q++) c[mi][ni][q] = 0.0f;
        } else if (i == n1 + 3) {
            // A = fp16(c + btop); reset c
#pragma unroll
            for (int mi = 0; mi < 2; mi++)
#pragma unroll
                for (int half = 0; half < 2; half++) {
                    int row = row0 + wm + mi * 16 + g + half * 8;
                    if (row < M) {
#pragma unroll
                        for (int ni = 0; ni < 8; ni++) {
                            int col = wn + ni * 8 + tg * 2;
                            float vx = c[mi][ni][half * 2 + 0] + btop[col];
                            float vy = c[mi][ni][half * 2 + 1] + btop[col + 1];
                            *(__half2*)(Aout + (size_t)row * 128 + col) =
                                __floats2half2_rn(vx, vy);
                        }
                    }
                }
#pragma unroll
            for (int mi = 0; mi < 2; mi++)
#pragma unroll
                for (int ni = 0; ni < 8; ni++)
#pragma unroll
                    for (int q = 0; q < 4; q++) c[mi][ni][q] = 0.0f;
        } else if (i == total - 1) {
            // B = fp16(c)
#pragma unroll
            for (int mi = 0; mi < 2; mi++)
#pragma unroll
                for (int half = 0; half < 2; half++) {
                    int row = row0 + wm + mi * 16 + g + half * 8;
                    if (row < M) {
#pragma unroll
                        for (int ni = 0; ni < 8; ni++) {
                            int col = wn + ni * 8 + tg * 2;
                            *(__half2*)(Bout + (size_t)row * 128 + col) =
                                __floats2half2_rn(c[mi][ni][half * 2 + 0],
                                                  c[mi][ni][half * 2 + 1]);
                        }
                    }
                }
        }
    }
}

// ---------------------------------------------------------------------------
// Final-layer GEMM (fp16) + mean-pool numerator epilogue.
// ---------------------------------------------------------------------------
__global__ __launch_bounds__(256, 2)
void gemm_pool(const __half* __restrict__ Xh, const __half* __restrict__ W,
               const float* __restrict__ bias, int M,
               const int* __restrict__ batch, float* __restrict__ sums)
{
    __shared__ __half sH[128 * HSTR];
    __shared__ __half sW[4 * CHUNKH];
    const int tid  = threadIdx.x;
    const int warp = tid >> 5, lane = tid & 31;
    const int g  = lane >> 2;
    const int tg = lane & 3;
    const int wm = (warp >> 1) * 32;
    const int wn = (warp & 1) * 64;
    const int row0 = blockIdx.x * 128;

    {
        uint32_t xb = smem_u32(sH);
        const char* xs = (const char*)Xh;
        for (int s = tid; s < 128 * 16; s += 256) {
            int row = s >> 4, u = s & 15;
            cp16z(xb + (uint32_t)(row * (HSTR * 2) + u * 16),
                  xs + (size_t)(row0 + row) * 256 + u * 16,
                  (row0 + row < M) ? 16 : 0);
        }
        uint32_t wb = smem_u32(sW);
        const char* ws = (const char*)W;
        for (int s = tid; s < 4 * CHUNKH / 8; s += 256)
            cp16(wb + (uint32_t)s * 16, ws + s * 16);
    }
    CP_COMMIT();
    cp_wait<0>();
    __syncthreads();

    float c[2][8][4];
#pragma unroll
    for (int mi = 0; mi < 2; mi++)
#pragma unroll
        for (int ni = 0; ni < 8; ni++)
#pragma unroll
            for (int q = 0; q < 4; q++) c[mi][ni][q] = 0.0f;

#pragma unroll
    for (int i = 0; i < 4; i++)
        mma_chunk(c, sH, i * 32, &sW[i * CHUNKH], wm, wn, g, tg);

#pragma unroll
    for (int mi = 0; mi < 2; mi++)
#pragma unroll
        for (int half = 0; half < 2; half++) {
            int row = row0 + wm + mi * 16 + g + half * 8;
            if (row < M) {
                int gsel = __ldg(batch + row);
#pragma unroll
                for (int ni = 0; ni < 8; ni++) {
                    int col = wn + ni * 8 + tg * 2;
                    float ox = fmaxf(c[mi][ni][half * 2 + 0] + bias[col],     0.f);
                    float oy = fmaxf(c[mi][ni][half * 2 + 1] + bias[col + 1], 0.f);
                    float* p = sums + (size_t)gsel * 128 + col;
                    asm volatile("red.global.add.v2.f32 [%0], {%1,%2};"
                                 :: "l"(p), "f"(ox), "f"(oy) : "memory");
                }
            }
        }
}

// ---------------------------------------------------------------------------
// Weight conversion: src[m][k][n] fp32 -> fp16 chunks, transposed [n][k].
// ---------------------------------------------------------------------------
__global__ void k_cvt_w(const float* __restrict__ src, __half* __restrict__ dst, int nmat)
{
    int i = blockIdx.x * blockDim.x + threadIdx.x;
    if (i >= nmat * 16384) return;
    int m = i >> 14, rem = i & 16383;
    int k = rem >> 7, n = rem & 127;
    dst[(size_t)m * MATH + (k >> 5) * CHUNKH + n * BSTR + (k & 31)] =
        __float2half_rn(src[i]);
}

__global__ void k_cvt_proj(const float* __restrict__ src, __half* __restrict__ dst, int K)
{
    int i = blockIdx.x * blockDim.x + threadIdx.x;
    if (i >= K * 128) return;
    int k = i >> 7, n = i & 127;
    dst[(k >> 5) * CHUNKH + n * BSTR + (k & 31)] = __float2half_rn(src[i]);
}

// ---------------------------------------------------------------------------
// CSR build
// ---------------------------------------------------------------------------
__global__ void k_count(const int* __restrict__ ei, int E, int* __restrict__ cnt)
{
    int i = blockIdx.x * blockDim.x + threadIdx.x;
    if (i < E) atomicAdd(cnt + __ldg(ei + E + i), 1);
}

__global__ void scan_block(int* __restrict__ data, int n, int* __restrict__ bsums)
{
    __shared__ int s[1024];
    int t = threadIdx.x;
    int i = blockIdx.x * 1024 + t;
    int v = (i < n) ? data[i] : 0;
    s[t] = v; __syncthreads();
    for (int d = 1; d < 1024; d <<= 1) {
        int x = (t >= d) ? s[t - d] : 0;
        __syncthreads();
        s[t] += x;
        __syncthreads();
    }
    if (i < n) data[i] = s[t] - v;
    if (t == 1023) bsums[blockIdx.x] = s[1023];
}

__global__ void scan_tops(int* __restrict__ bsums, int nb)
{
    __shared__ int s[128];
    int t = threadIdx.x;
    int v = (t < nb) ? bsums[t] : 0;
    s[t] = v; __syncthreads();
    for (int d = 1; d < 128; d <<= 1) {
        int x = (t >= d) ? s[t - d] : 0;
        __syncthreads();
        s[t] += x;
        __syncthreads();
    }
    if (t < nb) bsums[t] = s[t] - v;
}

__global__ void scan_add(int* __restrict__ data, int n,
                         const int* __restrict__ bsums, int total)
{
    int i = blockIdx.x * 1024 + threadIdx.x;
    if (i < n) data[i] += bsums[blockIdx.x];
    if (i == 0) data[n] = total;
}

__global__ void k_fill(const int* __restrict__ ei, int E,
                       int* __restrict__ cursor, int* __restrict__ csrsrc)
{
    int i = blockIdx.x * blockDim.x + threadIdx.x;
    if (i < E) {
        int d = __ldg(ei + E + i);
        int s = __ldg(ei + i);
        int p = atomicAdd(cursor + d, 1);
        csrsrc[p] = s;
    }
}

// ---------------------------------------------------------------------------
// aggr[i] = fp16( sum_e relu(A[i] + B[src_e]) ), fp32 accumulation.
// A/B fp16 rows; lane covers 4 columns (uint2 = 4 halves).
// ---------------------------------------------------------------------------
__global__ void csr_agg(const int* __restrict__ rowptr, const int* __restrict__ csrsrc,
                        const __half* __restrict__ A, const __half* __restrict__ B,
                        __half* __restrict__ aggr, int n)
{
    int w = (blockIdx.x * blockDim.x + threadIdx.x) >> 5;
    int lane = threadIdx.x & 31;
    if (w >= n) return;
    int s0 = __ldg(rowptr + w), s1 = __ldg(rowptr + w + 1);

    uint2 ar = *(const uint2*)(A + (size_t)w * 128 + lane * 4);
    float2 a01 = __half22float2(*(__half2*)&ar.x);
    float2 a23 = __half22float2(*(__half2*)&ar.y);

    float4 acc0 = make_float4(0.f, 0.f, 0.f, 0.f);
    float4 acc1 = make_float4(0.f, 0.f, 0.f, 0.f);
    int e = s0;
    for (; e + 2 <= s1; e += 2) {
        int i0 = __ldg(csrsrc + e);
        int i1 = __ldg(csrsrc + e + 1);
        uint2 b0 = *(const uint2*)(B + (size_t)i0 * 128 + lane * 4);
        uint2 b1 = *(const uint2*)(B + (size_t)i1 * 128 + lane * 4);
        float2 b001 = __half22float2(*(__half2*)&b0.x);
        float2 b023 = __half22float2(*(__half2*)&b0.y);
        float2 b101 = __half22float2(*(__half2*)&b1.x);
        float2 b123 = __half22float2(*(__half2*)&b1.y);
        acc0.x += fmaxf(a01.x + b001.x, 0.f); acc0.y += fmaxf(a01.y + b001.y, 0.f);
        acc0.z += fmaxf(a23.x + b023.x, 0.f); acc0.w += fmaxf(a23.y + b023.y, 0.f);
        acc1.x += fmaxf(a01.x + b101.x, 0.f); acc1.y += fmaxf(a01.y + b101.y, 0.f);
        acc1.z += fmaxf(a23.x + b123.x, 0.f); acc1.w += fmaxf(a23.y + b123.y, 0.f);
    }
    if (e < s1) {
        int s = __ldg(csrsrc + e);
        uint2 b0 = *(const uint2*)(B + (size_t)s * 128 + lane * 4);
        float2 b001 = __half22float2(*(__half2*)&b0.x);
        float2 b023 = __half22float2(*(__half2*)&b0.y);
        acc0.x += fmaxf(a01.x + b001.x, 0.f); acc0.y += fmaxf(a01.y + b001.y, 0.f);
        acc0.z += fmaxf(a23.x + b023.x, 0.f); acc0.w += fmaxf(a23.y + b023.y, 0.f);
    }
    __half2 h0 = __floats2half2_rn(acc0.x + acc1.x, acc0.y + acc1.y);
    __half2 h1 = __floats2half2_rn(acc0.z + acc1.z, acc0.w + acc1.w);
    uint2 o;
    o.x = *(uint32_t*)&h0;
    o.y = *(uint32_t*)&h1;
    *(uint2*)(aggr + (size_t)w * 128 + lane * 4) = o;
}

// ---------------------------------------------------------------------------
__global__ void pool_cnt(const int* __restrict__ batch, int n, float* __restrict__ cnt)
{
    int i = blockIdx.x * blockDim.x + threadIdx.x;
    if (i < n) atomicAdd(cnt + __ldg(batch + i), 1.0f);
}

__global__ void pool_div(const float* __restrict__ sums, const float* __restrict__ cnt,
                         float* __restrict__ fused, int colofs)
{
    int g = blockIdx.x, c = threadIdx.x;
    float cc = fmaxf(cnt[g], 1.0f);
    fused[(size_t)g * 256 + colofs + c] = sums[(size_t)g * 128 + c] / cc;
}

__global__ void head_kernel(const float* __restrict__ fused,
                            const float* __restrict__ mu_w, const float* __restrict__ mu_b,
                            const float* __restrict__ lv_w, const float* __restrict__ lv_b,
                            float* __restrict__ mu_out, float* __restrict__ lv_out)
{
    __shared__ float sf[256];
    int g = blockIdx.x, t = threadIdx.x;
    sf[t]       = fused[(size_t)g * 256 + t];
    sf[t + 128] = fused[(size_t)g * 256 + 128 + t];
    __syncthreads();
    if (t < 112) {
        bool is_mu = (t < 56);
        int j = is_mu ? t : t - 56;
        const float* Wp = is_mu ? mu_w : lv_w;
        float acc = is_mu ? mu_b[j] : lv_b[j];
#pragma unroll 8
        for (int k = 0; k < 256; k++) acc += sf[k] * Wp[k * ZD + j];
        if (is_mu) mu_out[(size_t)g * ZD + j] = acc;
        else       lv_out[(size_t)g * ZD + j] = acc;
    }
}

// ---------------------------------------------------------------------------
struct Scratch {
    __half *A, *B, *aggr, *wt;
    float *sums, *cnt;
    int *rowptr, *cursor, *csrsrc, *bsums;
};

static void csr_build(cudaStream_t st, const Scratch& S, const int* ei, int E, int n)
{
    int nb  = (n + 1023) / 1024;
    int ebk = (E + 255) / 256;
    cudaMemsetAsync(S.rowptr, 0, (size_t)(n + 1) * sizeof(int), st);
    k_count<<<ebk, 256, 0, st>>>(ei, E, S.rowptr);
    scan_block<<<nb, 1024, 0, st>>>(S.rowptr, n, S.bsums);
    scan_tops<<<1, 128, 0, st>>>(S.bsums, nb);
    scan_add<<<nb, 1024, 0, st>>>(S.rowptr, n, S.bsums, E);
    cudaMemcpyAsync(S.cursor, S.rowptr, (size_t)n * sizeof(int),
                    cudaMemcpyDeviceToDevice, st);
    k_fill<<<ebk, 256, 0, st>>>(ei, E, S.cursor, S.csrsrc);
}

static void encode_main(cudaStream_t st, const Scratch& S,
                        const float* x, int n, int din,
                        const int* batch, const float* pw, const float* pb,
                        const float* mw, const float* mb,
                        const float* lw, const float* lb,
                        float* fused, int colofs, cudaEvent_t ev_csr)
{
    int gb  = (n + 127) / 128;
    int wbk = (int)(((long long)n * 32 + 255) / 256);

    __half* wproj = S.wt;
    __half* wmsg  = S.wt + (size_t)(din / 32) * CHUNKH;
    __half* wlin  = wmsg + (size_t)6 * MATH;
    k_cvt_proj<<<(din * 128 + 255) / 256, 256, 0, st>>>(pw, wproj, din);
    k_cvt_w<<<(6 * 16384 + 255) / 256, 256, 0, st>>>(mw, wmsg, 6);
    k_cvt_w<<<(3 * 16384 + 255) / 256, 256, 0, st>>>(lw, wlin, 3);

    fused_layer<<<gb, 256, 0, st>>>(x, din, n, 1, wproj, pb,
                                    wmsg, mb, wmsg + MATH, S.A, S.B);
    if (ev_csr) cudaStreamWaitEvent(st, ev_csr, 0);
    csr_agg<<<wbk, 256, 0, st>>>(S.rowptr, S.csrsrc, S.A, S.B, S.aggr, n);

    for (int l = 1; l < 3; l++) {
        fused_layer<<<gb, 256, 0, st>>>(S.aggr, 128, n, 0,
                                        wlin + (size_t)(l - 1) * MATH, lb + (l - 1) * 128,
                                        wmsg + (size_t)(2 * l) * MATH, mb + l * 128,
                                        wmsg + (size_t)(2 * l + 1) * MATH, S.A, S.B);
        csr_agg<<<wbk, 256, 0, st>>>(S.rowptr, S.csrsrc, S.A, S.B, S.aggr, n);
    }

    cudaMemsetAsync(S.sums, 0, (size_t)NGRAPHS * 128 * sizeof(float), st);
    gemm_pool<<<gb, 256, 0, st>>>(S.aggr, wlin + (size_t)2 * MATH, lb + 2 * 128,
                                  n, batch, S.sums);
    cudaMemsetAsync(S.cnt, 0, (size_t)NGRAPHS * sizeof(float), st);
    pool_cnt<<<(n + 255) / 256, 256, 0, st>>>(batch, n, S.cnt);
    pool_div<<<NGRAPHS, 128, 0, st>>>(S.sums, S.cnt, fused, colofs);
}

extern "C" void kernel_launch(void* const* d_in, const int* in_sizes, int n_in,
                              void* d_out, int out_size)
{
    const float* tree_x      = (const float*)d_in[0];
    const int*   tree_ei     = (const int*)  d_in[1];
    const float* graph_x     = (const float*)d_in[2];
    const int*   graph_ei    = (const int*)  d_in[3];
    const int*   batch_tree  = (const int*)  d_in[4];
    const int*   batch_graph = (const int*)  d_in[5];
    const float* t_proj_w = (const float*)d_in[6];
    const float* t_proj_b = (const float*)d_in[7];
    const float* t_msg_w  = (const float*)d_in[8];
    const float* t_msg_b  = (const float*)d_in[9];
    const float* t_lin_w  = (const float*)d_in[10];
    const float* t_lin_b  = (const float*)d_in[11];
    const float* gr_proj_w = (const float*)d_in[12];
    const float* gr_proj_b = (const float*)d_in[13];
    const float* gr_msg_w  = (const float*)d_in[14];
    const float* gr_msg_b  = (const float*)d_in[15];
    const float* gr_lin_w  = (const float*)d_in[16];
    const float* gr_lin_b  = (const float*)d_in[17];
    const float* mu_w = (const float*)d_in[18];
    const float* mu_b = (const float*)d_in[19];
    const float* lv_w = (const float*)d_in[20];
    const float* lv_b = (const float*)d_in[21];
    float* out = (float*)d_out;

    const int n_tree  = in_sizes[0] / 64;
    const int e_tree  = in_sizes[1] / 2;
    const int n_graph = in_sizes[2] / 32;
    const int e_graph = in_sizes[3] / 2;

    Scratch G, T;
    cudaGetSymbolAddress((void**)&G.A,      g_A);
    cudaGetSymbolAddress((void**)&G.B,      g_B);
    cudaGetSymbolAddress((void**)&G.aggr,   g_aggr);
    cudaGetSymbolAddress((void**)&G.sums,   g_sums);
    cudaGetSymbolAddress((void**)&G.cnt,    g_cnt);
    cudaGetSymbolAddress((void**)&G.wt,     g_wt);
    cudaGetSymbolAddress((void**)&G.rowptr, g_rowptr);
    cudaGetSymbolAddress((void**)&G.cursor, g_cursor);
    cudaGetSymbolAddress((void**)&G.csrsrc, g_csrsrc);
    cudaGetSymbolAddress((void**)&G.bsums,  g_bsums);
    cudaGetSymbolAddress((void**)&T.A,      t_A);
    cudaGetSymbolAddress((void**)&T.B,      t_B);
    cudaGetSymbolAddress((void**)&T.aggr,   t_aggr);
    cudaGetSymbolAddress((void**)&T.sums,   t_sums);
    cudaGetSymbolAddress((void**)&T.cnt,    t_cnt);
    cudaGetSymbolAddress((void**)&T.wt,     t_wt);
    cudaGetSymbolAddress((void**)&T.rowptr, t_rowptr);
    cudaGetSymbolAddress((void**)&T.cursor, t_cursor);
    cudaGetSymbolAddress((void**)&T.csrsrc, t_csrsrc);
    cudaGetSymbolAddress((void**)&T.bsums,  t_bsums);

    static cudaStream_t s_tree = nullptr, s_csr = nullptr;
    static cudaEvent_t ev_fork = nullptr, ev_join = nullptr, ev_csr = nullptr;
    if (!s_tree) {
        cudaStreamCreateWithFlags(&s_tree, cudaStreamNonBlocking);
        cudaStreamCreateWithFlags(&s_csr, cudaStreamNonBlocking);
        cudaEventCreateWithFlags(&ev_fork, cudaEventDisableTiming);
        cudaEventCreateWithFlags(&ev_join, cudaEventDisableTiming);
        cudaEventCreateWithFlags(&ev_csr, cudaEventDisableTiming);
    }

    float* fused = out + 2 * NGRAPHS * ZD;   // output layout: mu | logvar | fused

    cudaEventRecord(ev_fork, 0);
    cudaStreamWaitEvent(s_tree, ev_fork, 0);
    cudaStreamWaitEvent(s_csr, ev_fork, 0);

    csr_build(s_tree, T, tree_ei, e_tree, n_tree);
    encode_main(s_tree, T, tree_x, n_tree, 64, batch_tree,
                t_proj_w, t_proj_b, t_msg_w, t_msg_b, t_lin_w, t_lin_b,
                fused, 0, nullptr);

    csr_build(s_csr, G, graph_ei, e_graph, n_graph);
    cudaEventRecord(ev_csr, s_csr);
    encode_main(0, G, graph_x, n_graph, 32, batch_graph,
                gr_proj_w, gr_proj_b, gr_msg_w, gr_msg_b, gr_lin_w, gr_lin_b,
                fused, 128, ev_csr);

    cudaEventRecord(ev_join, s_tree);
    cudaStreamWaitEvent(0, ev_join, 0);

    head_kernel<<<NGRAPHS, 128>>>(fused, mu_w, mu_b, lv_w, lv_b,
                                  out, out + NGRAPHS * ZD);
}

// round 12
// speedup vs baseline: 1.5483x; 1.0265x over previous
#include <cuda_runtime.h>
#include <cuda_fp16.h>
#include <cstdint>

#define NGRAPHS 1024
#define ZD 56

// ---- graph-encoder scratch ----
__device__ __half g_A   [100000 * 128];
__device__ __half g_B   [100000 * 128];
__device__ __half g_aggr[100000 * 128];
__device__ float  g_sums[NGRAPHS * 128];
__device__ float  g_cnt [NGRAPHS];
__device__ int    g_rowptr[100001];
__device__ int    g_cursor[100001];
__device__ int    g_csrsrc[400000];
__device__ int    g_bsums[128];
__device__ __half g_wt  [240000];
// ---- tree-encoder scratch ----
__device__ __half t_A   [20000 * 128];
__device__ __half t_B   [20000 * 128];
__device__ __half t_aggr[20000 * 128];
__device__ float  t_sums[NGRAPHS * 128];
__device__ float  t_cnt [NGRAPHS];
__device__ int    t_rowptr[20001];
__device__ int    t_cursor[20001];
__device__ int    t_csrsrc[40000];
__device__ int    t_bsums[128];
__device__ __half t_wt  [240000];

#define HSTR 136                  // halves per sH row (272 B)
#define BSTR 40                   // halves per weight-chunk row (80 B, 32 used)
#define CHUNKH (128 * BSTR)       // 5120 halves per 32-k chunk
#define MATH   (4 * CHUNKH)       // halves per 128x128 matrix

__device__ __forceinline__ uint32_t smem_u32(const void* p) {
    return (uint32_t)__cvta_generic_to_shared(p);
}
__device__ __forceinline__ void cp16(uint32_t dst, const void* src) {
    asm volatile("cp.async.cg.shared.global [%0], [%1], 16;" :: "r"(dst), "l"(src));
}
__device__ __forceinline__ void cp16z(uint32_t dst, const void* src, int srcsz) {
    asm volatile("cp.async.cg.shared.global [%0], [%1], 16, %2;"
                 :: "r"(dst), "l"(src), "r"(srcsz));
}
#define CP_COMMIT() asm volatile("cp.async.commit_group;")
template<int N> __device__ __forceinline__ void cp_wait() {
    asm volatile("cp.async.wait_group %0;" :: "n"(N));
}

// fp16 m16n8k16 MMAs over one 32-k chunk.
__device__ __forceinline__ void mma_chunk(float c[2][8][4],
                                          const __half* __restrict__ sH, int hk0,
                                          const __half* __restrict__ sW,
                                          int wm, int wn, int g, int tg)
{
#pragma unroll
    for (int kk = 0; kk < 2; kk++) {
        uint32_t a[2][4], b[8][2];
#pragma unroll
        for (int mi = 0; mi < 2; mi++) {
            int base = (wm + mi * 16 + g) * HSTR + hk0 + kk * 16 + tg * 2;
            a[mi][0] = *(const uint32_t*)&sH[base];
            a[mi][1] = *(const uint32_t*)&sH[base + 8 * HSTR];
            a[mi][2] = *(const uint32_t*)&sH[base + 8];
            a[mi][3] = *(const uint32_t*)&sH[base + 8 * HSTR + 8];
        }
#pragma unroll
        for (int ni = 0; ni < 8; ni++) {
            int wb = (wn + ni * 8 + g) * BSTR + kk * 16 + tg * 2;
            b[ni][0] = *(const uint32_t*)&sW[wb];
            b[ni][1] = *(const uint32_t*)&sW[wb + 8];
        }
#pragma unroll
        for (int mi = 0; mi < 2; mi++)
#pragma unroll
            for (int ni = 0; ni < 8; ni++) {
                asm volatile(
                    "mma.sync.aligned.m16n8k16.row.col.f32.f16.f16.f32 "
                    "{%0,%1,%2,%3},{%4,%5,%6,%7},{%8,%9},{%0,%1,%2,%3};"
                    : "+f"(c[mi][ni][0]), "+f"(c[mi][ni][1]),
                      "+f"(c[mi][ni][2]), "+f"(c[mi][ni][3])
                    : "r"(a[mi][0]), "r"(a[mi][1]), "r"(a[mi][2]), "r"(a[mi][3]),
                      "r"(b[ni][0]), "r"(b[ni][1]));
            }
    }
}

// ---------------------------------------------------------------------------
// Fused node update with 3-buffer weight pipeline (ONE barrier per chunk).
// ---------------------------------------------------------------------------
__global__ __launch_bounds__(256, 2)
void fused_layer(const void* __restrict__ Xv, int K, int M, int xcvt,
                 const __half* __restrict__ Wmain, const float* __restrict__ bmain,
                 const __half* __restrict__ Wtop,  const float* __restrict__ btop,
                 const __half* __restrict__ Wbot,
                 __half* __restrict__ Aout, __half* __restrict__ Bout)
{
    __shared__ __half sH[128 * HSTR];
    __shared__ __half sW[3][CHUNKH];
    const int tid  = threadIdx.x;
    const int warp = tid >> 5, lane = tid & 31;
    const int g  = lane >> 2;
    const int tg = lane & 3;
    const int wm = (warp >> 1) * 32;
    const int wn = (warp & 1) * 64;
    const int row0 = blockIdx.x * 128;

    const int n1 = K >> 5;
    const int total = n1 + 8;

    auto wsrc = [&](int i) -> const __half* {
        if (i < n1) return Wmain + (size_t)i * CHUNKH;
        int j = i - n1;
        return (j < 4) ? (Wtop + (size_t)j * CHUNKH) : (Wbot + (size_t)(j - 4) * CHUNKH);
    };
    auto issue_w = [&](int i, int buf) {
        const char* src = (const char*)wsrc(i);
        uint32_t base = smem_u32(&sW[buf][0]);
        for (int s = tid; s < CHUNKH / 8; s += 256)
            cp16(base + (uint32_t)s * 16, src + s * 16);
    };

    if (!xcvt) {   // X = fp16 aggr rows (128 halves): raw async copy (group 0)
        uint32_t base = smem_u32(sH);
        const char* xh = (const char*)Xv;
        for (int s = tid; s < 128 * 16; s += 256) {
            int row = s >> 4, u = s & 15;
            cp16z(base + (uint32_t)(row * (HSTR * 2) + u * 16),
                  xh + (size_t)(row0 + row) * 256 + u * 16,
                  (row0 + row < M) ? 16 : 0);
        }
    }
    issue_w(0, 0); CP_COMMIT();
    issue_w(1, 1); CP_COMMIT();
    if (xcvt) {    // layer 0: raw fp32 input -> fp16 (K = 32 or 64)
        const float* X = (const float*)Xv;
        for (int i = tid; i < 128 * K; i += 256) {
            int r = (K == 32) ? (i >> 5) : (i >> 6);
            int k = i & (K - 1);
            int row = row0 + r;
            float v = (row < M) ? X[(size_t)row * K + k] : 0.0f;
            sH[r * HSTR + k] = __float2half_rn(v);
        }
    }

    float c[2][8][4];
#pragma unroll
    for (int mi = 0; mi < 2; mi++)
#pragma unroll
        for (int ni = 0; ni < 8; ni++)
#pragma unroll
            for (int q = 0; q < 4; q++) c[mi][ni][q] = 0.0f;

    for (int i = 0; i < total; i++) {
        if (i == total - 1) cp_wait<0>(); else cp_wait<1>();
        __syncthreads();                       // data ready + buffer (i+2)%3 free
        if (i + 2 < total) { issue_w(i + 2, (i + 2) % 3); CP_COMMIT(); }
        int hk0 = ((i < n1) ? i : ((i - n1) & 3)) * 32;
        mma_chunk(c, sH, hk0, &sW[i % 3][0], wm, wn, g, tg);

        if (i == n1 - 1) {
            // h = relu(c + bmain) -> sH (fp16); readers separated by next sync
#pragma unroll
            for (int mi = 0; mi < 2; mi++)
#pragma unroll
                for (int half = 0; half < 2; half++) {
                    int r = wm + mi * 16 + g + half * 8;
#pragma unroll
                    for (int ni = 0; ni < 8; ni++) {
                        int col = wn + ni * 8 + tg * 2;
                        float vx = fmaxf(c[mi][ni][half * 2 + 0] + bmain[col],     0.f);
                        float vy = fmaxf(c[mi][ni][half * 2 + 1] + bmain[col + 1], 0.f);
                        *(__half2*)&sH[r * HSTR + col] = __floats2half2_rn(vx, vy);
                    }
                }
#pragma unroll
            for (int mi = 0; mi < 2; mi++)
#pragma unroll
                for (int ni = 0; ni < 8; ni++)
#pragma unroll
                    for (int q = 0; q < 4; q++) c[mi][ni][q] = 0.0f;
        } else if (i == n1 + 3) {
            // A = fp16(c + btop); reset c
#pragma unroll
            for (int mi = 0; mi < 2; mi++)
#pragma unroll
                for (int half = 0; half < 2; half++) {
                    int row = row0 + wm + mi * 16 + g + half * 8;
                    if (row < M) {
#pragma unroll
                        for (int ni = 0; ni < 8; ni++) {
                            int col = wn + ni * 8 + tg * 2;
                            float vx = c[mi][ni][half * 2 + 0] + btop[col];
                            float vy = c[mi][ni][half * 2 + 1] + btop[col + 1];
                            *(__half2*)(Aout + (size_t)row * 128 + col) =
                                __floats2half2_rn(vx, vy);
                        }
                    }
                }
#pragma unroll
            for (int mi = 0; mi < 2; mi++)
#pragma unroll
                for (int ni = 0; ni < 8; ni++)
#pragma unroll
                    for (int q = 0; q < 4; q++) c[mi][ni][q] = 0.0f;
        } else if (i == total - 1) {
            // B = fp16(c)
#pragma unroll
            for (int mi = 0; mi < 2; mi++)
#pragma unroll
                for (int half = 0; half < 2; half++) {
                    int row = row0 + wm + mi * 16 + g + half * 8;
                    if (row < M) {
#pragma unroll
                        for (int ni = 0; ni < 8; ni++) {
                            int col = wn + ni * 8 + tg * 2;
                            *(__half2*)(Bout + (size_t)row * 128 + col) =
                                __floats2half2_rn(c[mi][ni][half * 2 + 0],
                                                  c[mi][ni][half * 2 + 1]);
                        }
                    }
                }
        }
    }
}

// ---------------------------------------------------------------------------
// Final-layer GEMM (fp16) + mean-pool numerator epilogue.
// ---------------------------------------------------------------------------
__global__ __launch_bounds__(256, 2)
void gemm_pool(const __half* __restrict__ Xh, const __half* __restrict__ W,
               const float* __restrict__ bias, int M,
               const int* __restrict__ batch, float* __restrict__ sums)
{
    __shared__ __half sH[128 * HSTR];
    __shared__ __half sW[4 * CHUNKH];
    const int tid  = threadIdx.x;
    const int warp = tid >> 5, lane = tid & 31;
    const int g  = lane >> 2;
    const int tg = lane & 3;
    const int wm = (warp >> 1) * 32;
    const int wn = (warp & 1) * 64;
    const int row0 = blockIdx.x * 128;

    {
        uint32_t xb = smem_u32(sH);
        const char* xs = (const char*)Xh;
        for (int s = tid; s < 128 * 16; s += 256) {
            int row = s >> 4, u = s & 15;
            cp16z(xb + (uint32_t)(row * (HSTR * 2) + u * 16),
                  xs + (size_t)(row0 + row) * 256 + u * 16,
                  (row0 + row < M) ? 16 : 0);
        }
        uint32_t wb = smem_u32(sW);
        const char* ws = (const char*)W;
        for (int s = tid; s < 4 * CHUNKH / 8; s += 256)
            cp16(wb + (uint32_t)s * 16, ws + s * 16);
    }
    CP_COMMIT();
    cp_wait<0>();
    __syncthreads();

    float c[2][8][4];
#pragma unroll
    for (int mi = 0; mi < 2; mi++)
#pragma unroll
        for (int ni = 0; ni < 8; ni++)
#pragma unroll
            for (int q = 0; q < 4; q++) c[mi][ni][q] = 0.0f;

#pragma unroll
    for (int i = 0; i < 4; i++)
        mma_chunk(c, sH, i * 32, &sW[i * CHUNKH], wm, wn, g, tg);

#pragma unroll
    for (int mi = 0; mi < 2; mi++)
#pragma unroll
        for (int half = 0; half < 2; half++) {
            int row = row0 + wm + mi * 16 + g + half * 8;
            if (row < M) {
                int gsel = __ldg(batch + row);
#pragma unroll
                for (int ni = 0; ni < 8; ni++) {
                    int col = wn + ni * 8 + tg * 2;
                    float ox = fmaxf(c[mi][ni][half * 2 + 0] + bias[col],     0.f);
                    float oy = fmaxf(c[mi][ni][half * 2 + 1] + bias[col + 1], 0.f);
                    float* p = sums + (size_t)gsel * 128 + col;
                    asm volatile("red.global.add.v2.f32 [%0], {%1,%2};"
                                 :: "l"(p), "f"(ox), "f"(oy) : "memory");
                }
            }
        }
}

// ---------------------------------------------------------------------------
// Weight conversion: src[m][k][n] fp32 -> fp16 chunks, transposed [n][k].
// ---------------------------------------------------------------------------
__global__ void k_cvt_w(const float* __restrict__ src, __half* __restrict__ dst, int nmat)
{
    int i = blockIdx.x * blockDim.x + threadIdx.x;
    if (i >= nmat * 16384) return;
    int m = i >> 14, rem = i & 16383;
    int k = rem >> 7, n = rem & 127;
    dst[(size_t)m * MATH + (k >> 5) * CHUNKH + n * BSTR + (k & 31)] =
        __float2half_rn(src[i]);
}

__global__ void k_cvt_proj(const float* __restrict__ src, __half* __restrict__ dst, int K)
{
    int i = blockIdx.x * blockDim.x + threadIdx.x;
    if (i >= K * 128) return;
    int k = i >> 7, n = i & 127;
    dst[(k >> 5) * CHUNKH + n * BSTR + (k & 31)] = __float2half_rn(src[i]);
}

// ---------------------------------------------------------------------------
// CSR build
// ---------------------------------------------------------------------------
__global__ void k_count(const int* __restrict__ ei, int E, int* __restrict__ cnt)
{
    int i = blockIdx.x * blockDim.x + threadIdx.x;
    if (i < E) atomicAdd(cnt + __ldg(ei + E + i), 1);
}

__global__ void scan_block(int* __restrict__ data, int n, int* __restrict__ bsums)
{
    __shared__ int s[1024];
    int t = threadIdx.x;
    int i = blockIdx.x * 1024 + t;
    int v = (i < n) ? data[i] : 0;
    s[t] = v; __syncthreads();
    for (int d = 1; d < 1024; d <<= 1) {
        int x = (t >= d) ? s[t - d] : 0;
        __syncthreads();
        s[t] += x;
        __syncthreads();
    }
    if (i < n) data[i] = s[t] - v;
    if (t == 1023) bsums[blockIdx.x] = s[1023];
}

__global__ void scan_tops(int* __restrict__ bsums, int nb)
{
    __shared__ int s[128];
    int t = threadIdx.x;
    int v = (t < nb) ? bsums[t] : 0;
    s[t] = v; __syncthreads();
    for (int d = 1; d < 128; d <<= 1) {
        int x = (t >= d) ? s[t - d] : 0;
        __syncthreads();
        s[t] += x;
        __syncthreads();
    }
    if (t < nb) bsums[t] = s[t] - v;
}

__global__ void scan_add(int* __restrict__ data, int n,
                         const int* __restrict__ bsums, int total)
{
    int i = blockIdx.x * 1024 + threadIdx.x;
    if (i < n) data[i] += bsums[blockIdx.x];
    if (i == 0) data[n] = total;
}

__global__ void k_fill(const int* __restrict__ ei, int E,
                       int* __restrict__ cursor, int* __restrict__ csrsrc)
{
    int i = blockIdx.x * blockDim.x + threadIdx.x;
    if (i < E) {
        int d = __ldg(ei + E + i);
        int s = __ldg(ei + i);
        int p = atomicAdd(cursor + d, 1);
        csrsrc[p] = s;
    }
}

// ---------------------------------------------------------------------------
// aggr[i] = fp16( sum_e relu(A[i] + B[src_e]) ), fp32 accumulation.
// ---------------------------------------------------------------------------
__global__ void csr_agg(const int* __restrict__ rowptr, const int* __restrict__ csrsrc,
                        const __half* __restrict__ A, const __half* __restrict__ B,
                        __half* __restrict__ aggr, int n)
{
    int w = (blockIdx.x * blockDim.x + threadIdx.x) >> 5;
    int lane = threadIdx.x & 31;
    if (w >= n) return;
    int s0 = __ldg(rowptr + w), s1 = __ldg(rowptr + w + 1);

    uint2 ar = *(const uint2*)(A + (size_t)w * 128 + lane * 4);
    float2 a01 = __half22float2(*(__half2*)&ar.x);
    float2 a23 = __half22float2(*(__half2*)&ar.y);

    float4 acc0 = make_float4(0.f, 0.f, 0.f, 0.f);
    float4 acc1 = make_float4(0.f, 0.f, 0.f, 0.f);
    int e = s0;
    for (; e + 2 <= s1; e += 2) {
        int i0 = __ldg(csrsrc + e);
        int i1 = __ldg(csrsrc + e + 1);
        uint2 b0 = *(const uint2*)(B + (size_t)i0 * 128 + lane * 4);
        uint2 b1 = *(const uint2*)(B + (size_t)i1 * 128 + lane * 4);
        float2 b001 = __half22float2(*(__half2*)&b0.x);
        float2 b023 = __half22float2(*(__half2*)&b0.y);
        float2 b101 = __half22float2(*(__half2*)&b1.x);
        float2 b123 = __half22float2(*(__half2*)&b1.y);
        acc0.x += fmaxf(a01.x + b001.x, 0.f); acc0.y += fmaxf(a01.y + b001.y, 0.f);
        acc0.z += fmaxf(a23.x + b023.x, 0.f); acc0.w += fmaxf(a23.y + b023.y, 0.f);
        acc1.x += fmaxf(a01.x + b101.x, 0.f); acc1.y += fmaxf(a01.y + b101.y, 0.f);
        acc1.z += fmaxf(a23.x + b123.x, 0.f); acc1.w += fmaxf(a23.y + b123.y, 0.f);
    }
    if (e < s1) {
        int s = __ldg(csrsrc + e);
        uint2 b0 = *(const uint2*)(B + (size_t)s * 128 + lane * 4);
        float2 b001 = __half22float2(*(__half2*)&b0.x);
        float2 b023 = __half22float2(*(__half2*)&b0.y);
        acc0.x += fmaxf(a01.x + b001.x, 0.f); acc0.y += fmaxf(a01.y + b001.y, 0.f);
        acc0.z += fmaxf(a23.x + b023.x, 0.f); acc0.w += fmaxf(a23.y + b023.y, 0.f);
    }
    __half2 h0 = __floats2half2_rn(acc0.x + acc1.x, acc0.y + acc1.y);
    __half2 h1 = __floats2half2_rn(acc0.z + acc1.z, acc0.w + acc1.w);
    uint2 o;
    o.x = *(uint32_t*)&h0;
    o.y = *(uint32_t*)&h1;
    *(uint2*)(aggr + (size_t)w * 128 + lane * 4) = o;
}

// ---------------------------------------------------------------------------
__global__ void pool_cnt(const int* __restrict__ batch, int n, float* __restrict__ cnt)
{
    int i = blockIdx.x * blockDim.x + threadIdx.x;
    if (i < n) atomicAdd(cnt + __ldg(batch + i), 1.0f);
}

// Fused: fused = [sumsT/cntT | sumsG/cntG]; mu/logvar heads.
__global__ void head2_kernel(const float* __restrict__ sumsT, const float* __restrict__ cntT,
                             const float* __restrict__ sumsG, const float* __restrict__ cntG,
                             const float* __restrict__ mu_w, const float* __restrict__ mu_b,
                             const float* __restrict__ lv_w, const float* __restrict__ lv_b,
                             float* __restrict__ mu_out, float* __restrict__ lv_out,
                             float* __restrict__ fused_out)
{
    __shared__ float sf[256];
    int g = blockIdx.x, t = threadIdx.x;
    float ct = fmaxf(cntT[g], 1.0f);
    float cg = fmaxf(cntG[g], 1.0f);
    float vT = sumsT[(size_t)g * 128 + t] / ct;
    float vG = sumsG[(size_t)g * 128 + t] / cg;
    sf[t] = vT;
    sf[t + 128] = vG;
    fused_out[(size_t)g * 256 + t]       = vT;
    fused_out[(size_t)g * 256 + 128 + t] = vG;
    __syncthreads();
    if (t < 112) {
        bool is_mu = (t < 56);
        int j = is_mu ? t : t - 56;
        const float* Wp = is_mu ? mu_w : lv_w;
        float acc = is_mu ? mu_b[j] : lv_b[j];
#pragma unroll 8
        for (int k = 0; k < 256; k++) acc += sf[k] * Wp[k * ZD + j];
        if (is_mu) mu_out[(size_t)g * ZD + j] = acc;
        else       lv_out[(size_t)g * ZD + j] = acc;
    }
}

// ---------------------------------------------------------------------------
struct Scratch {
    __half *A, *B, *aggr, *wt;
    float *sums, *cnt;
    int *rowptr, *cursor, *csrsrc, *bsums;
};

static void pool_prep(cudaStream_t st, const Scratch& S, const int* batch, int n)
{
    cudaMemsetAsync(S.sums, 0, (size_t)NGRAPHS * 128 * sizeof(float), st);
    cudaMemsetAsync(S.cnt,  0, (size_t)NGRAPHS * sizeof(float), st);
    pool_cnt<<<(n + 255) / 256, 256, 0, st>>>(batch, n, S.cnt);
}

static void csr_build(cudaStream_t st, const Scratch& S, const int* ei, int E, int n)
{
    int nb  = (n + 1023) / 1024;
    int ebk = (E + 255) / 256;
    cudaMemsetAsync(S.rowptr, 0, (size_t)(n + 1) * sizeof(int), st);
    k_count<<<ebk, 256, 0, st>>>(ei, E, S.rowptr);
    scan_block<<<nb, 1024, 0, st>>>(S.rowptr, n, S.bsums);
    scan_tops<<<1, 128, 0, st>>>(S.bsums, nb);
    scan_add<<<nb, 1024, 0, st>>>(S.rowptr, n, S.bsums, E);
    cudaMemcpyAsync(S.cursor, S.rowptr, (size_t)n * sizeof(int),
                    cudaMemcpyDeviceToDevice, st);
    k_fill<<<ebk, 256, 0, st>>>(ei, E, S.cursor, S.csrsrc);
}

static void encode_main(cudaStream_t st, const Scratch& S,
                        const float* x, int n, int din,
                        const int* batch, const float* pw, const float* pb,
                        const float* mw, const float* mb,
                        const float* lw, const float* lb, cudaEvent_t ev_csr)
{
    int gb  = (n + 127) / 128;
    int wbk = (int)(((long long)n * 32 + 255) / 256);

    __half* wproj = S.wt;
    __half* wmsg  = S.wt + (size_t)(din / 32) * CHUNKH;
    __half* wlin  = wmsg + (size_t)6 * MATH;
    k_cvt_proj<<<(din * 128 + 255) / 256, 256, 0, st>>>(pw, wproj, din);
    k_cvt_w<<<(6 * 16384 + 255) / 256, 256, 0, st>>>(mw, wmsg, 6);
    k_cvt_w<<<(3 * 16384 + 255) / 256, 256, 0, st>>>(lw, wlin, 3);

    fused_layer<<<gb, 256, 0, st>>>(x, din, n, 1, wproj, pb,
                                    wmsg, mb, wmsg + MATH, S.A, S.B);
    if (ev_csr) cudaStreamWaitEvent(st, ev_csr, 0);
    csr_agg<<<wbk, 256, 0, st>>>(S.rowptr, S.csrsrc, S.A, S.B, S.aggr, n);

    for (int l = 1; l < 3; l++) {
        fused_layer<<<gb, 256, 0, st>>>(S.aggr, 128, n, 0,
                                        wlin + (size_t)(l - 1) * MATH, lb + (l - 1) * 128,
                                        wmsg + (size_t)(2 * l) * MATH, mb + l * 128,
                                        wmsg + (size_t)(2 * l + 1) * MATH, S.A, S.B);
        csr_agg<<<wbk, 256, 0, st>>>(S.rowptr, S.csrsrc, S.A, S.B, S.aggr, n);
    }

    gemm_pool<<<gb, 256, 0, st>>>(S.aggr, wlin + (size_t)2 * MATH, lb + 2 * 128,
                                  n, batch, S.sums);
}

extern "C" void kernel_launch(void* const* d_in, const int* in_sizes, int n_in,
                              void* d_out, int out_size)
{
    const float* tree_x      = (const float*)d_in[0];
    const int*   tree_ei     = (const int*)  d_in[1];
    const float* graph_x     = (const float*)d_in[2];
    const int*   graph_ei    = (const int*)  d_in[3];
    const int*   batch_tree  = (const int*)  d_in[4];
    const int*   batch_graph = (const int*)  d_in[5];
    const float* t_proj_w = (const float*)d_in[6];
    const float* t_proj_b = (const float*)d_in[7];
    const float* t_msg_w  = (const float*)d_in[8];
    const float* t_msg_b  = (const float*)d_in[9];
    const float* t_lin_w  = (const float*)d_in[10];
    const float* t_lin_b  = (const float*)d_in[11];
    const float* gr_proj_w = (const float*)d_in[12];
    const float* gr_proj_b = (const float*)d_in[13];
    const float* gr_msg_w  = (const float*)d_in[14];
    const float* gr_msg_b  = (const float*)d_in[15];
    const float* gr_lin_w  = (const float*)d_in[16];
    const float* gr_lin_b  = (const float*)d_in[17];
    const float* mu_w = (const float*)d_in[18];
    const float* mu_b = (const float*)d_in[19];
    const float* lv_w = (const float*)d_in[20];
    const float* lv_b = (const float*)d_in[21];
    float* out = (float*)d_out;

    const int n_tree  = in_sizes[0] / 64;
    const int e_tree  = in_sizes[1] / 2;
    const int n_graph = in_sizes[2] / 32;
    const int e_graph = in_sizes[3] / 2;

    Scratch G, T;
    cudaGetSymbolAddress((void**)&G.A,      g_A);
    cudaGetSymbolAddress((void**)&G.B,      g_B);
    cudaGetSymbolAddress((void**)&G.aggr,   g_aggr);
    cudaGetSymbolAddress((void**)&G.sums,   g_sums);
    cudaGetSymbolAddress((void**)&G.cnt,    g_cnt);
    cudaGetSymbolAddress((void**)&G.wt,     g_wt);
    cudaGetSymbolAddress((void**)&G.rowptr, g_rowptr);
    cudaGetSymbolAddress((void**)&G.cursor, g_cursor);
    cudaGetSymbolAddress((void**)&G.csrsrc, g_csrsrc);
    cudaGetSymbolAddress((void**)&G.bsums,  g_bsums);
    cudaGetSymbolAddress((void**)&T.A,      t_A);
    cudaGetSymbolAddress((void**)&T.B,      t_B);
    cudaGetSymbolAddress((void**)&T.aggr,   t_aggr);
    cudaGetSymbolAddress((void**)&T.sums,   t_sums);
    cudaGetSymbolAddress((void**)&T.cnt,    t_cnt);
    cudaGetSymbolAddress((void**)&T.wt,     t_wt);
    cudaGetSymbolAddress((void**)&T.rowptr, t_rowptr);
    cudaGetSymbolAddress((void**)&T.cursor, t_cursor);
    cudaGetSymbolAddress((void**)&T.csrsrc, t_csrsrc);
    cudaGetSymbolAddress((void**)&T.bsums,  t_bsums);

    static cudaStream_t s_tree = nullptr, s_csr = nullptr;
    static cudaEvent_t ev_fork = nullptr, ev_join = nullptr, ev_csr = nullptr;
    if (!s_tree) {
        cudaStreamCreateWithFlags(&s_tree, cudaStreamNonBlocking);
        cudaStreamCreateWithFlags(&s_csr, cudaStreamNonBlocking);
        cudaEventCreateWithFlags(&ev_fork, cudaEventDisableTiming);
        cudaEventCreateWithFlags(&ev_join, cudaEventDisableTiming);
        cudaEventCreateWithFlags(&ev_csr, cudaEventDisableTiming);
    }

    float* fused = out + 2 * NGRAPHS * ZD;   // output layout: mu | logvar | fused

    cudaEventRecord(ev_fork, 0);
    cudaStreamWaitEvent(s_tree, ev_fork, 0);
    cudaStreamWaitEvent(s_csr, ev_fork, 0);

    // Tree branch: pool prep + CSR + encoder (hidden under graph work).
    pool_prep(s_tree, T, batch_tree, n_tree);
    csr_build(s_tree, T, tree_ei, e_tree, n_tree);
    encode_main(s_tree, T, tree_x, n_tree, 64, batch_tree,
                t_proj_w, t_proj_b, t_msg_w, t_msg_b, t_lin_w, t_lin_b, nullptr);

    // Graph: pool prep + CSR on side stream, overlapped with layer-0 GEMM.
    pool_prep(s_csr, G, batch_graph, n_graph);
    csr_build(s_csr, G, graph_ei, e_graph, n_graph);
    cudaEventRecord(ev_csr, s_csr);
    encode_main(0, G, graph_x, n_graph, 32, batch_graph,
                gr_proj_w, gr_proj_b, gr_msg_w, gr_msg_b, gr_lin_w, gr_lin_b, ev_csr);

    cudaEventRecord(ev_join, s_tree);
    cudaStreamWaitEvent(0, ev_join, 0);

    head2_kernel<<<NGRAPHS, 128>>>(T.sums, T.cnt, G.sums, G.cnt,
                                   mu_w, mu_b, lv_w, lv_b,
                                   out, out + NGRAPHS * ZD, fused);
}